// round 6
// baseline (speedup 1.0000x reference)
#include <cuda_runtime.h>
#include <cuda_fp16.h>
#include <cstdint>

// Problem constants (fixed by the dataset)
#define NL0 8000
#define NL1 4000
#define NL2 2000
#define NTOT 14000
#define FDIM 128
#define NCOL 384

static constexpr float ADJ_SCALE = 4096.0f;
static constexpr float INV_SCALE = 1.0f / 4096.0f;

// ---------------- device scratch (static, no allocations) ----------------
__device__ __half g_hh[NTOT * FDIM];       // h0|h1|h2 fp16
__device__ __half g_wcat[3 * FDIM * NCOL]; // per-j: [128][384] with col block i
__device__ __half g_T[NTOT * NCOL];        // T_j = h_j @ Wcat_j
__device__ __half g_Y[NTOT * NCOL];        // gathered/scattered B operand [k][384]
__device__ int    g_inv0[NL0];
__device__ int    g_inv1[NL1];

__device__ __forceinline__ void cp16(__half* dst, const void* src, bool full) {
    unsigned d = (unsigned)__cvta_generic_to_shared(dst);
    int n = full ? 16 : 0;
    asm volatile("cp.async.cg.shared.global [%0], [%1], 16, %2;\n" :: "r"(d), "l"(src), "r"(n));
}

// ---------------- prep kernels ----------------
__global__ void k_prep_h(const float* __restrict__ h0, const float* __restrict__ h1,
                         const float* __restrict__ h2, const float* __restrict__ Ws) {
    int t = blockIdx.x * blockDim.x + threadIdx.x;
    if (t < 448000) {
        int e = t * 4;
        const float* src;
        if (e < 1024000) src = h0 + e;
        else if (e < 1536000) src = h1 + (e - 1024000);
        else src = h2 + (e - 1536000);
        float4 v = *(const float4*)src;
        *(__half2*)(g_hh + e)     = __floats2half2_rn(v.x, v.y);
        *(__half2*)(g_hh + e + 2) = __floats2half2_rn(v.z, v.w);
    }
    if (t < 3 * FDIM * NCOL) {
        int j = t / 49152;
        int rem = t % 49152;
        int k = rem / 384;
        int col = rem % 384;
        int i = col >> 7;
        int c = col & 127;
        g_wcat[t] = __float2half(Ws[(((size_t)(i * 3 + j) * 128) + k) * 128 + c]);
    }
    if (t < NL0) g_inv0[t] = -1;
    if (t < NL1) g_inv1[t] = -1;
}

__global__ void k_scatter_inv(const int* __restrict__ idx0, const int* __restrict__ idx1) {
    int t = blockIdx.x * blockDim.x + threadIdx.x;
    if (t < NL1) g_inv0[idx0[t]] = t;
    if (t < NL2) g_inv1[idx1[t]] = t;
}

// Gather T -> Y (one 16B chunk per thread)
__global__ void k_gather_y(const int* __restrict__ idx0, const int* __restrict__ idx1) {
    int tid = blockIdx.x * blockDim.x + threadIdx.x;
    if (tid >= NTOT * 3 * 16) return;
    int seg = tid & 15;
    int rest = tid >> 4;
    int j = rest % 3;
    int rg = rest / 3;
    int i, r;
    if (rg < NL0)            { i = 0; r = rg; }
    else if (rg < NL0 + NL1) { i = 1; r = rg - NL0; }
    else                     { i = 2; r = rg - NL0 - NL1; }
    int s = -1;
    if (i == 0) {
        if (j == 0) s = r;
        else if (j == 1) s = g_inv0[r];
        else { int t0 = g_inv0[r]; s = (t0 >= 0) ? g_inv1[t0] : -1; }
    } else if (i == 1) {
        if (j == 0) s = idx0[r];
        else if (j == 1) s = r;
        else s = g_inv1[r];
    } else {
        if (j == 0) s = idx0[idx1[r]];
        else if (j == 1) s = idx1[r];
        else s = r;
    }
    uint4 v = make_uint4(0u, 0u, 0u, 0u);
    if (s >= 0) {
        int srow = (j == 0 ? 0 : (j == 1 ? NL0 : NL0 + NL1)) + s;
        v = *(const uint4*)(g_T + (size_t)srow * NCOL + i * 128 + seg * 8);
    }
    *(uint4*)(g_Y + (size_t)rg * NCOL + j * 128 + seg * 8) = v;
}

// ---------------- shared GEMM tiling constants (R1-proven) ----------------
#define BM 64
#define BK 32
#define APITCH 40   // halves per A smem row (pad 8)
#define BPITCH 392  // halves per B smem row (pad 8)
#define STG_HALVES (BM * APITCH + BK * BPITCH)  // 15104
#define SMEM1_BYTES (3 * STG_HALVES * 2)        // 90624
#define SMEM2_BYTES 100352                      // max(90624, 64*392*4)

// ---------------- stage-1 GEMM (R1-proven): T = h @ Wcat, fp16 in/out ----------------
struct Gemm1Seg { int M, tileStart; long long Aoff, Boff, Coff; };
struct Gemm1Cfg { Gemm1Seg seg[3]; };

__global__ void __launch_bounds__(256, 1) k_gemm1(Gemm1Cfg cfg) {
    extern __shared__ __align__(16) char smem_raw[];
    __half* smem = (__half*)smem_raw;

    int tid = threadIdx.x;
    int bx = blockIdx.x;
    int s = 0;
    if (bx >= cfg.seg[1].tileStart) s = 1;
    if (bx >= cfg.seg[2].tileStart) s = 2;
    Gemm1Seg sg = cfg.seg[s];
    int tile = bx - sg.tileStart;
    int row0 = tile * BM;
    int M = sg.M, K = 128;
    const __half* A = g_hh + sg.Aoff;
    const __half* B = g_wcat + sg.Boff;

    int lane = tid & 31, wid = tid >> 5;
    int wm = wid >> 2, wn = wid & 3;

    int am = tid >> 2, aseg = tid & 3;
    int br[6], bseg[6];
#pragma unroll
    for (int it = 0; it < 6; ++it) { int c = tid + it * 256; br[it] = c / 48; bseg[it] = c % 48; }

    int KT = K / BK; // 4

    auto load_tile = [&](int kt, int st) {
        __half* as = smem + st * STG_HALVES;
        __half* bs = as + BM * APITCH;
        int k0 = kt * BK;
        {
            int grow = row0 + am;
            bool p = (grow < M);
            const __half* src = p ? (A + (size_t)grow * K + k0 + aseg * 8) : A;
            cp16(as + am * APITCH + aseg * 8, src, p);
        }
#pragma unroll
        for (int it = 0; it < 6; ++it) {
            int kr = k0 + br[it];
            cp16(bs + br[it] * BPITCH + bseg[it] * 8, B + (size_t)kr * NCOL + bseg[it] * 8, true);
        }
    };

    load_tile(0, 0);
    asm volatile("cp.async.commit_group;\n");
    load_tile(1, 1);
    asm volatile("cp.async.commit_group;\n");

    float acc[2][12][4] = {};
    int a_row = lane & 15;
    int a_col8 = 8 * (lane >> 4);
    int b_row = lane & 15;

    for (int kt = 0; kt < KT; ++kt) {
        asm volatile("cp.async.wait_group 1;\n");
        __syncthreads();
        int nx = kt + 2;
        if (nx < KT) load_tile(nx, nx % 3);
        asm volatile("cp.async.commit_group;\n");

        __half* as = smem + (kt % 3) * STG_HALVES;
        __half* bs = as + BM * APITCH;
#pragma unroll
        for (int kk = 0; kk < 2; ++kk) {
            uint32_t a[2][4];
#pragma unroll
            for (int mt = 0; mt < 2; ++mt) {
                __half* p = as + (size_t)(wm * 32 + mt * 16 + a_row) * APITCH + kk * 16 + a_col8;
                unsigned sp = (unsigned)__cvta_generic_to_shared(p);
                asm volatile("ldmatrix.sync.aligned.m8n8.x4.shared.b16 {%0,%1,%2,%3}, [%4];\n"
                             : "=r"(a[mt][0]), "=r"(a[mt][1]), "=r"(a[mt][2]), "=r"(a[mt][3])
                             : "r"(sp));
            }
#pragma unroll
            for (int nt = 0; nt < 12; ++nt) {
                uint32_t b0, b1;
                __half* p = bs + (size_t)(kk * 16 + b_row) * BPITCH + wn * 96 + nt * 8;
                unsigned sp = (unsigned)__cvta_generic_to_shared(p);
                asm volatile("ldmatrix.sync.aligned.m8n8.x2.trans.shared.b16 {%0,%1}, [%2];\n"
                             : "=r"(b0), "=r"(b1) : "r"(sp));
#pragma unroll
                for (int mt = 0; mt < 2; ++mt) {
                    asm volatile(
                        "mma.sync.aligned.m16n8k16.row.col.f32.f16.f16.f32 "
                        "{%0,%1,%2,%3}, {%4,%5,%6,%7}, {%8,%9}, {%0,%1,%2,%3};\n"
                        : "+f"(acc[mt][nt][0]), "+f"(acc[mt][nt][1]),
                          "+f"(acc[mt][nt][2]), "+f"(acc[mt][nt][3])
                        : "r"(a[mt][0]), "r"(a[mt][1]), "r"(a[mt][2]), "r"(a[mt][3]),
                          "r"(b0), "r"(b1));
                }
            }
        }
    }

    int g = lane >> 2, tg = lane & 3;
    __half* C = g_T + sg.Coff;
#pragma unroll
    for (int mt = 0; mt < 2; ++mt) {
        int r1 = row0 + wm * 32 + mt * 16 + g;
        int r2 = r1 + 8;
#pragma unroll
        for (int nt = 0; nt < 12; ++nt) {
            int col = wn * 96 + nt * 8 + tg * 2;
            if (r1 < M) *(__half2*)(C + (size_t)r1 * NCOL + col) =
                __floats2half2_rn(acc[mt][nt][0], acc[mt][nt][1]);
            if (r2 < M) *(__half2*)(C + (size_t)r2 * NCOL + col) =
                __floats2half2_rn(acc[mt][nt][2], acc[mt][nt][3]);
        }
    }
}

// ---------------- stage-2 GEMM: out = sum_j relu((adj@Y)*inv + b) ----------------
// A: fp32 adj, converted in-register (x4096) with +2-stage software pipeline.
// B: fp16 Y via cp.async (R1-identical). Fused relu/bias/sum epilogue via smem.
// K tail (2000 % 32 = 16) handled by zero-fill predicates on both operands.
struct Gemm2Seg { const float* A; int M, tileStart; long long Boff; int rowBase, lvl; };
struct Gemm2Cfg { Gemm2Seg seg[3]; };

__global__ void __launch_bounds__(256, 1) k_gemm2(Gemm2Cfg cfg,
                                                  const float* __restrict__ bsp,
                                                  float* __restrict__ out) {
    extern __shared__ __align__(16) char smem_raw[];
    __half* smem = (__half*)smem_raw;

    int tid = threadIdx.x;
    int bx = blockIdx.x;
    int s = 0;
    if (bx >= cfg.seg[1].tileStart) s = 1;
    if (bx >= cfg.seg[2].tileStart) s = 2;
    Gemm2Seg sg = cfg.seg[s];
    int tile = bx - sg.tileStart;
    int row0 = tile * BM;
    int M = sg.M, K = sg.M;          // square adj
    const float* A = sg.A;
    const __half* B = g_Y + sg.Boff;

    int lane = tid & 31, wid = tid >> 5;
    int wm = wid >> 2, wn = wid & 3;

    // A: 64x32 fp32 tile; per thread two adjacent float4 (8 floats = one 16B half STS)
    int am = tid >> 2, aseg = tid & 3;
    // B: same as R1
    int br[6], bseg[6];
#pragma unroll
    for (int it = 0; it < 6; ++it) { int c = tid + it * 256; br[it] = c / 48; bseg[it] = c % 48; }

    int KT = (K + BK - 1) / BK;  // ceil: K=2000 -> 63 (tail 16 cols, zero-filled)

    auto ldA = [&](int kt, float4* v) {
        int grow = row0 + am;
        int gcol = kt * BK + aseg * 8;
        // gcol is 8-aligned and K % 8 == 0, so gcol < K covers all 8 elements
        if (grow < M && gcol < K) {
            const float* src = A + (size_t)grow * K + gcol;
            v[0] = *(const float4*)src;
            v[1] = *(const float4*)(src + 4);
        } else {
            v[0] = make_float4(0.f, 0.f, 0.f, 0.f);
            v[1] = make_float4(0.f, 0.f, 0.f, 0.f);
        }
    };
    auto stsA = [&](int st, const float4* v) {
        __half* as = smem + st * STG_HALVES;
        uint4 p;
        *(__half2*)&p.x = __floats2half2_rn(v[0].x * ADJ_SCALE, v[0].y * ADJ_SCALE);
        *(__half2*)&p.y = __floats2half2_rn(v[0].z * ADJ_SCALE, v[0].w * ADJ_SCALE);
        *(__half2*)&p.z = __floats2half2_rn(v[1].x * ADJ_SCALE, v[1].y * ADJ_SCALE);
        *(__half2*)&p.w = __floats2half2_rn(v[1].z * ADJ_SCALE, v[1].w * ADJ_SCALE);
        *(uint4*)(as + am * APITCH + aseg * 8) = p;
    };
    auto loadB = [&](int kt, int st) {
        __half* bs = smem + st * STG_HALVES + BM * APITCH;
        int k0 = kt * BK;
#pragma unroll
        for (int it = 0; it < 6; ++it) {
            int kr = k0 + br[it];
            bool p = (kr < K);
            const __half* src = p ? (B + (size_t)kr * NCOL + bseg[it] * 8) : B;
            cp16(bs + br[it] * BPITCH + bseg[it] * 8, src, p);
        }
    };

    // prologue: STS at iter kt uses aregs[(kt+1)&1]; LDG at iter kt fills aregs[kt&1] for kt+2
    float4 aregs[2][2];
    ldA(0, aregs[0]); stsA(0, aregs[0]);
    ldA(1, aregs[1]);
    loadB(0, 0);
    asm volatile("cp.async.commit_group;\n");
    loadB(1, 1);
    asm volatile("cp.async.commit_group;\n");

    float acc[2][12][4] = {};
    int a_row = lane & 15;
    int a_col8 = 8 * (lane >> 4);
    int b_row = lane & 15;

    for (int kt = 0; kt < KT; ++kt) {
        asm volatile("cp.async.wait_group 1;\n");
        __syncthreads();
        if (kt + 1 < KT) stsA((kt + 1) % 3, aregs[(kt + 1) & 1]);
        if (kt + 2 < KT) {
            ldA(kt + 2, aregs[kt & 1]);
            loadB(kt + 2, (kt + 2) % 3);
        }
        asm volatile("cp.async.commit_group;\n");

        __half* as = smem + (kt % 3) * STG_HALVES;
        __half* bs = as + BM * APITCH;
#pragma unroll
        for (int kk = 0; kk < 2; ++kk) {
            uint32_t a[2][4];
#pragma unroll
            for (int mt = 0; mt < 2; ++mt) {
                __half* p = as + (size_t)(wm * 32 + mt * 16 + a_row) * APITCH + kk * 16 + a_col8;
                unsigned sp = (unsigned)__cvta_generic_to_shared(p);
                asm volatile("ldmatrix.sync.aligned.m8n8.x4.shared.b16 {%0,%1,%2,%3}, [%4];\n"
                             : "=r"(a[mt][0]), "=r"(a[mt][1]), "=r"(a[mt][2]), "=r"(a[mt][3])
                             : "r"(sp));
            }
#pragma unroll
            for (int nt = 0; nt < 12; ++nt) {
                uint32_t b0, b1;
                __half* p = bs + (size_t)(kk * 16 + b_row) * BPITCH + wn * 96 + nt * 8;
                unsigned sp = (unsigned)__cvta_generic_to_shared(p);
                asm volatile("ldmatrix.sync.aligned.m8n8.x2.trans.shared.b16 {%0,%1}, [%2];\n"
                             : "=r"(b0), "=r"(b1) : "r"(sp));
#pragma unroll
                for (int mt = 0; mt < 2; ++mt) {
                    asm volatile(
                        "mma.sync.aligned.m16n8k16.row.col.f32.f16.f16.f32 "
                        "{%0,%1,%2,%3}, {%4,%5,%6,%7}, {%8,%9}, {%0,%1,%2,%3};\n"
                        : "+f"(acc[mt][nt][0]), "+f"(acc[mt][nt][1]),
                          "+f"(acc[mt][nt][2]), "+f"(acc[mt][nt][3])
                        : "r"(a[mt][0]), "r"(a[mt][1]), "r"(a[mt][2]), "r"(a[mt][3]),
                          "r"(b0), "r"(b1));
                }
            }
        }
    }

    // ---- fused epilogue: relu(acc*inv + b) into smem, then cross-j sum ----
    asm volatile("cp.async.wait_group 0;\n");
    __syncthreads();   // all warps done with pipeline smem

    float* zbuf = (float*)smem_raw;        // [64][392] fp32
    const float* bias = bsp + sg.lvl * 3 * FDIM;  // contiguous 384 floats for this level
    int g = lane >> 2, tg = lane & 3;
#pragma unroll
    for (int mt = 0; mt < 2; ++mt) {
        int rl1 = wm * 32 + mt * 16 + g;
        int rl2 = rl1 + 8;
#pragma unroll
        for (int nt = 0; nt < 12; ++nt) {
            int col = wn * 96 + nt * 8 + tg * 2;
            float b0v = bias[col], b1v = bias[col + 1];
            zbuf[rl1 * 392 + col]     = fmaxf(acc[mt][nt][0] * INV_SCALE + b0v, 0.f);
            zbuf[rl1 * 392 + col + 1] = fmaxf(acc[mt][nt][1] * INV_SCALE + b1v, 0.f);
            zbuf[rl2 * 392 + col]     = fmaxf(acc[mt][nt][2] * INV_SCALE + b0v, 0.f);
            zbuf[rl2 * 392 + col + 1] = fmaxf(acc[mt][nt][3] * INV_SCALE + b1v, 0.f);
        }
    }
    __syncthreads();

#pragma unroll
    for (int u = 0; u < 8; ++u) {
        int idx = tid + 256 * u;           // 2048 float4 slots: row(0..63) x c4(0..31)
        int row = idx >> 5;
        int c4 = idx & 31;
        if (row0 + row < M) {
            const float* zr = zbuf + row * 392 + c4 * 4;
            float4 v0 = *(const float4*)zr;
            float4 v1 = *(const float4*)(zr + 128);
            float4 v2 = *(const float4*)(zr + 256);
            float4 o;
            o.x = v0.x + v1.x + v2.x;
            o.y = v0.y + v1.y + v2.y;
            o.z = v0.z + v1.z + v2.z;
            o.w = v0.w + v1.w + v2.w;
            *(float4*)(out + (size_t)(sg.rowBase + row0 + row) * FDIM + c4 * 4) = o;
        }
    }
}

// ---------------- host launch ----------------
extern "C" void kernel_launch(void* const* d_in, const int* in_sizes, int n_in,
                              void* d_out, int out_size) {
    const float* adj0 = (const float*)d_in[0];
    const float* adj1 = (const float*)d_in[1];
    const float* adj2 = (const float*)d_in[2];
    const float* h0   = (const float*)d_in[3];
    const float* h1   = (const float*)d_in[4];
    const float* h2   = (const float*)d_in[5];
    const int*   idx0 = (const int*)d_in[6];
    const int*   idx1 = (const int*)d_in[7];
    const float* Ws   = (const float*)d_in[8];
    const float* bsp  = (const float*)d_in[9];
    float* out = (float*)d_out;

    cudaFuncSetAttribute(k_gemm1, cudaFuncAttributeMaxDynamicSharedMemorySize, SMEM1_BYTES);
    cudaFuncSetAttribute(k_gemm2, cudaFuncAttributeMaxDynamicSharedMemorySize, SMEM2_BYTES);

    k_prep_h<<<1750, 256>>>(h0, h1, h2, Ws);
    k_scatter_inv<<<16, 256>>>(idx0, idx1);

    Gemm1Cfg c1;
    c1.seg[0] = { NL0, 0,   0,       0,     0 };
    c1.seg[1] = { NL1, 125, 1024000, 49152, 3072000 };
    c1.seg[2] = { NL2, 188, 1536000, 98304, 4608000 };
    k_gemm1<<<220, 256, SMEM1_BYTES>>>(c1);

    k_gather_y<<<2625, 256>>>(idx0, idx1);

    Gemm2Cfg c2;
    c2.seg[0] = { adj0, NL0, 0,   0,                          0,          0 };
    c2.seg[1] = { adj1, NL1, 125, (long long)NL0 * NCOL,      NL0,        1 };
    c2.seg[2] = { adj2, NL2, 188, (long long)12000 * NCOL,    NL0 + NL1,  2 };
    k_gemm2<<<220, 256, SMEM2_BYTES>>>(c2, bsp, out);
}

// round 8
// speedup vs baseline: 1.2918x; 1.2918x over previous
#include <cuda_runtime.h>
#include <cuda_fp16.h>
#include <cstdint>

// Problem constants (fixed by the dataset)
#define NL0 8000
#define NL1 4000
#define NL2 2000
#define NTOT 14000
#define FDIM 128
#define NCOL 384

static constexpr float ADJ_SCALE = 4096.0f;
static constexpr float INV_SCALE = 1.0f / 4096.0f;

// ---------------- device scratch (static, no allocations) ----------------
__device__ __half g_adjh[84000000];        // adj0|adj1|adj2 in fp16, scaled
__device__ __half g_hh[NTOT * FDIM];       // h0|h1|h2 fp16
__device__ __half g_wcat[3 * FDIM * NCOL]; // per-j: [128][384] with col block i
__device__ __half g_T[NTOT * NCOL];        // T_j = h_j @ Wcat_j
__device__ __half g_Y[NTOT * NCOL];        // gathered/scattered B operand [k][384]
__device__ int    g_inv0[NL0];
__device__ int    g_inv1[NL1];

__device__ __forceinline__ void cp16(__half* dst, const void* src, bool full) {
    unsigned d = (unsigned)__cvta_generic_to_shared(dst);
    int n = full ? 16 : 0;
    asm volatile("cp.async.cg.shared.global [%0], [%1], 16, %2;\n" :: "r"(d), "l"(src), "r"(n));
}

// ---------------- prep kernels (R1-proven) ----------------
__global__ void k_prep_h(const float* __restrict__ h0, const float* __restrict__ h1,
                         const float* __restrict__ h2, const float* __restrict__ Ws) {
    int t = blockIdx.x * blockDim.x + threadIdx.x;
    if (t < 448000) {
        int e = t * 4;
        const float* src;
        if (e < 1024000) src = h0 + e;
        else if (e < 1536000) src = h1 + (e - 1024000);
        else src = h2 + (e - 1536000);
        float4 v = *(const float4*)src;
        *(__half2*)(g_hh + e)     = __floats2half2_rn(v.x, v.y);
        *(__half2*)(g_hh + e + 2) = __floats2half2_rn(v.z, v.w);
    }
    if (t < 3 * FDIM * NCOL) {
        int j = t / 49152;
        int rem = t % 49152;
        int k = rem / 384;
        int col = rem % 384;
        int i = col >> 7;
        int c = col & 127;
        g_wcat[t] = __float2half(Ws[(((size_t)(i * 3 + j) * 128) + k) * 128 + c]);
    }
    if (t < NL0) g_inv0[t] = -1;
    if (t < NL1) g_inv1[t] = -1;
}

__global__ void k_scatter_inv(const int* __restrict__ idx0, const int* __restrict__ idx1) {
    int t = blockIdx.x * blockDim.x + threadIdx.x;
    if (t < NL1) g_inv0[idx0[t]] = t;
    if (t < NL2) g_inv1[idx1[t]] = t;
}

__global__ void k_convert_adj(const float* __restrict__ a0, const float* __restrict__ a1,
                              const float* __restrict__ a2) {
    int t = blockIdx.x * blockDim.x + threadIdx.x;
    if (t >= 21000000) return;
    long long e = (long long)t * 4;
    const float* src;
    if (e < 64000000LL) src = a0 + e;
    else if (e < 80000000LL) src = a1 + (e - 64000000LL);
    else src = a2 + (e - 80000000LL);
    float4 v = *(const float4*)src;
    *(__half2*)(g_adjh + e)     = __floats2half2_rn(v.x * ADJ_SCALE, v.y * ADJ_SCALE);
    *(__half2*)(g_adjh + e + 2) = __floats2half2_rn(v.z * ADJ_SCALE, v.w * ADJ_SCALE);
}

// Gather T -> Y (one 16B chunk per thread)
__global__ void k_gather_y(const int* __restrict__ idx0, const int* __restrict__ idx1) {
    int tid = blockIdx.x * blockDim.x + threadIdx.x;
    if (tid >= NTOT * 3 * 16) return;
    int seg = tid & 15;
    int rest = tid >> 4;
    int j = rest % 3;
    int rg = rest / 3;
    int i, r;
    if (rg < NL0)            { i = 0; r = rg; }
    else if (rg < NL0 + NL1) { i = 1; r = rg - NL0; }
    else                     { i = 2; r = rg - NL0 - NL1; }
    int s = -1;
    if (i == 0) {
        if (j == 0) s = r;
        else if (j == 1) s = g_inv0[r];
        else { int t0 = g_inv0[r]; s = (t0 >= 0) ? g_inv1[t0] : -1; }
    } else if (i == 1) {
        if (j == 0) s = idx0[r];
        else if (j == 1) s = r;
        else s = g_inv1[r];
    } else {
        if (j == 0) s = idx0[idx1[r]];
        else if (j == 1) s = idx1[r];
        else s = r;
    }
    uint4 v = make_uint4(0u, 0u, 0u, 0u);
    if (s >= 0) {
        int srow = (j == 0 ? 0 : (j == 1 ? NL0 : NL0 + NL1)) + s;
        v = *(const uint4*)(g_T + (size_t)srow * NCOL + i * 128 + seg * 8);
    }
    *(uint4*)(g_Y + (size_t)rg * NCOL + j * 128 + seg * 8) = v;
}

// ---------------- shared GEMM tiling constants (R1-proven) ----------------
#define BM 64
#define BK 32
#define APITCH 40   // halves per A smem row (pad 8)
#define BPITCH 392  // halves per B smem row (pad 8)
#define STG_HALVES (BM * APITCH + BK * BPITCH)  // 15104
#define SMEM1_BYTES (3 * STG_HALVES * 2)        // 90624
#define NSTG2 4
#define SMEM2_BYTES (NSTG2 * STG_HALVES * 2)    // 120832 (>= 64*392*4 zbuf)

// ---------------- stage-1 GEMM (R1-proven): T = h @ Wcat, fp16 in/out ----------------
struct Gemm1Seg { int M, tileStart; long long Aoff, Boff, Coff; };
struct Gemm1Cfg { Gemm1Seg seg[3]; };

__global__ void __launch_bounds__(256, 1) k_gemm1(Gemm1Cfg cfg) {
    extern __shared__ __align__(16) char smem_raw[];
    __half* smem = (__half*)smem_raw;

    int tid = threadIdx.x;
    int bx = blockIdx.x;
    int s = 0;
    if (bx >= cfg.seg[1].tileStart) s = 1;
    if (bx >= cfg.seg[2].tileStart) s = 2;
    Gemm1Seg sg = cfg.seg[s];
    int tile = bx - sg.tileStart;
    int row0 = tile * BM;
    int M = sg.M, K = 128;
    const __half* A = g_hh + sg.Aoff;
    const __half* B = g_wcat + sg.Boff;

    int lane = tid & 31, wid = tid >> 5;
    int wm = wid >> 2, wn = wid & 3;

    int am = tid >> 2, aseg = tid & 3;
    int br[6], bseg[6];
#pragma unroll
    for (int it = 0; it < 6; ++it) { int c = tid + it * 256; br[it] = c / 48; bseg[it] = c % 48; }

    int KT = K / BK; // 4

    auto load_tile = [&](int kt, int st) {
        __half* as = smem + st * STG_HALVES;
        __half* bs = as + BM * APITCH;
        int k0 = kt * BK;
        {
            int grow = row0 + am;
            bool p = (grow < M);
            const __half* src = p ? (A + (size_t)grow * K + k0 + aseg * 8) : A;
            cp16(as + am * APITCH + aseg * 8, src, p);
        }
#pragma unroll
        for (int it = 0; it < 6; ++it) {
            int kr = k0 + br[it];
            cp16(bs + br[it] * BPITCH + bseg[it] * 8, B + (size_t)kr * NCOL + bseg[it] * 8, true);
        }
    };

    load_tile(0, 0);
    asm volatile("cp.async.commit_group;\n");
    load_tile(1, 1);
    asm volatile("cp.async.commit_group;\n");

    float acc[2][12][4] = {};
    int a_row = lane & 15;
    int a_col8 = 8 * (lane >> 4);
    int b_row = lane & 15;

    for (int kt = 0; kt < KT; ++kt) {
        asm volatile("cp.async.wait_group 1;\n");
        __syncthreads();
        int nx = kt + 2;
        if (nx < KT) load_tile(nx, nx % 3);
        asm volatile("cp.async.commit_group;\n");

        __half* as = smem + (kt % 3) * STG_HALVES;
        __half* bs = as + BM * APITCH;
#pragma unroll
        for (int kk = 0; kk < 2; ++kk) {
            uint32_t a[2][4];
#pragma unroll
            for (int mt = 0; mt < 2; ++mt) {
                __half* p = as + (size_t)(wm * 32 + mt * 16 + a_row) * APITCH + kk * 16 + a_col8;
                unsigned sp = (unsigned)__cvta_generic_to_shared(p);
                asm volatile("ldmatrix.sync.aligned.m8n8.x4.shared.b16 {%0,%1,%2,%3}, [%4];\n"
                             : "=r"(a[mt][0]), "=r"(a[mt][1]), "=r"(a[mt][2]), "=r"(a[mt][3])
                             : "r"(sp));
            }
#pragma unroll
            for (int nt = 0; nt < 12; ++nt) {
                uint32_t b0, b1;
                __half* p = bs + (size_t)(kk * 16 + b_row) * BPITCH + wn * 96 + nt * 8;
                unsigned sp = (unsigned)__cvta_generic_to_shared(p);
                asm volatile("ldmatrix.sync.aligned.m8n8.x2.trans.shared.b16 {%0,%1}, [%2];\n"
                             : "=r"(b0), "=r"(b1) : "r"(sp));
#pragma unroll
                for (int mt = 0; mt < 2; ++mt) {
                    asm volatile(
                        "mma.sync.aligned.m16n8k16.row.col.f32.f16.f16.f32 "
                        "{%0,%1,%2,%3}, {%4,%5,%6,%7}, {%8,%9}, {%0,%1,%2,%3};\n"
                        : "+f"(acc[mt][nt][0]), "+f"(acc[mt][nt][1]),
                          "+f"(acc[mt][nt][2]), "+f"(acc[mt][nt][3])
                        : "r"(a[mt][0]), "r"(a[mt][1]), "r"(a[mt][2]), "r"(a[mt][3]),
                          "r"(b0), "r"(b1));
                }
            }
        }
    }

    int g = lane >> 2, tg = lane & 3;
    __half* C = g_T + sg.Coff;
#pragma unroll
    for (int mt = 0; mt < 2; ++mt) {
        int r1 = row0 + wm * 32 + mt * 16 + g;
        int r2 = r1 + 8;
#pragma unroll
        for (int nt = 0; nt < 12; ++nt) {
            int col = wn * 96 + nt * 8 + tg * 2;
            if (r1 < M) *(__half2*)(C + (size_t)r1 * NCOL + col) =
                __floats2half2_rn(acc[mt][nt][0], acc[mt][nt][1]);
            if (r2 < M) *(__half2*)(C + (size_t)r2 * NCOL + col) =
                __floats2half2_rn(acc[mt][nt][2], acc[mt][nt][3]);
        }
    }
}

// ---------------- stage-2 GEMM (R1 inner loop, 4 stages) + fused epilogue ----------------
// A: fp16 g_adjh via cp.async (R1-identical). out = sum_j relu((adj@Y)*inv + b).
struct Gemm2Seg { int M, tileStart; long long Aoff, Boff; int rowBase, lvl; };
struct Gemm2Cfg { Gemm2Seg seg[3]; };

__global__ void __launch_bounds__(256, 1) k_gemm2(Gemm2Cfg cfg,
                                                  const float* __restrict__ bsp,
                                                  float* __restrict__ out) {
    extern __shared__ __align__(16) char smem_raw[];
    __half* smem = (__half*)smem_raw;

    int tid = threadIdx.x;
    int bx = blockIdx.x;
    int s = 0;
    if (bx >= cfg.seg[1].tileStart) s = 1;
    if (bx >= cfg.seg[2].tileStart) s = 2;
    Gemm2Seg sg = cfg.seg[s];
    int tile = bx - sg.tileStart;
    int row0 = tile * BM;
    int M = sg.M, K = sg.M;          // square adj
    const __half* A = g_adjh + sg.Aoff;
    const __half* B = g_Y + sg.Boff;

    int lane = tid & 31, wid = tid >> 5;
    int wm = wid >> 2, wn = wid & 3;

    int am = tid >> 2, aseg = tid & 3;
    int br[6], bseg[6];
#pragma unroll
    for (int it = 0; it < 6; ++it) { int c = tid + it * 256; br[it] = c / 48; bseg[it] = c % 48; }

    int KT = (K + BK - 1) / BK;   // 250 / 125 / 63 (tail predicated)

    auto load_tile = [&](int kt, int st) {
        __half* as = smem + st * STG_HALVES;
        __half* bs = as + BM * APITCH;
        int k0 = kt * BK;
        {
            int grow = row0 + am;
            int gcol = k0 + aseg * 8;
            bool p = (grow < M) && (gcol < K);
            const __half* src = p ? (A + (size_t)grow * K + gcol) : A;
            cp16(as + am * APITCH + aseg * 8, src, p);
        }
#pragma unroll
        for (int it = 0; it < 6; ++it) {
            int kr = k0 + br[it];
            bool p = (kr < K);
            const __half* src = p ? (B + (size_t)kr * NCOL + bseg[it] * 8) : B;
            cp16(bs + br[it] * BPITCH + bseg[it] * 8, src, p);
        }
    };

    // prologue: fill 3 of 4 stages
    load_tile(0, 0);
    asm volatile("cp.async.commit_group;\n");
    load_tile(1, 1);
    asm volatile("cp.async.commit_group;\n");
    load_tile(2, 2);
    asm volatile("cp.async.commit_group;\n");

    float acc[2][12][4] = {};
    int a_row = lane & 15;
    int a_col8 = 8 * (lane >> 4);
    int b_row = lane & 15;

    for (int kt = 0; kt < KT; ++kt) {
        asm volatile("cp.async.wait_group 2;\n");
        __syncthreads();
        int nx = kt + 3;
        if (nx < KT) load_tile(nx, nx & 3);
        asm volatile("cp.async.commit_group;\n");

        __half* as = smem + (kt & 3) * STG_HALVES;
        __half* bs = as + BM * APITCH;
#pragma unroll
        for (int kk = 0; kk < 2; ++kk) {
            uint32_t a[2][4];
#pragma unroll
            for (int mt = 0; mt < 2; ++mt) {
                __half* p = as + (size_t)(wm * 32 + mt * 16 + a_row) * APITCH + kk * 16 + a_col8;
                unsigned sp = (unsigned)__cvta_generic_to_shared(p);
                asm volatile("ldmatrix.sync.aligned.m8n8.x4.shared.b16 {%0,%1,%2,%3}, [%4];\n"
                             : "=r"(a[mt][0]), "=r"(a[mt][1]), "=r"(a[mt][2]), "=r"(a[mt][3])
                             : "r"(sp));
            }
#pragma unroll
            for (int nt = 0; nt < 12; ++nt) {
                uint32_t b0, b1;
                __half* p = bs + (size_t)(kk * 16 + b_row) * BPITCH + wn * 96 + nt * 8;
                unsigned sp = (unsigned)__cvta_generic_to_shared(p);
                asm volatile("ldmatrix.sync.aligned.m8n8.x2.trans.shared.b16 {%0,%1}, [%2];\n"
                             : "=r"(b0), "=r"(b1) : "r"(sp));
#pragma unroll
                for (int mt = 0; mt < 2; ++mt) {
                    asm volatile(
                        "mma.sync.aligned.m16n8k16.row.col.f32.f16.f16.f32 "
                        "{%0,%1,%2,%3}, {%4,%5,%6,%7}, {%8,%9}, {%0,%1,%2,%3};\n"
                        : "+f"(acc[mt][nt][0]), "+f"(acc[mt][nt][1]),
                          "+f"(acc[mt][nt][2]), "+f"(acc[mt][nt][3])
                        : "r"(a[mt][0]), "r"(a[mt][1]), "r"(a[mt][2]), "r"(a[mt][3]),
                          "r"(b0), "r"(b1));
                }
            }
        }
    }

    // ---- fused epilogue: relu(acc*inv + b) into smem, then cross-j sum ----
    asm volatile("cp.async.wait_group 0;\n");
    __syncthreads();   // all warps done with pipeline smem

    float* zbuf = (float*)smem_raw;        // [64][392] fp32 (fits in 120832 B)
    const float* bias = bsp + sg.lvl * 3 * FDIM;  // contiguous 384 floats for this level
    int g = lane >> 2, tg = lane & 3;
#pragma unroll
    for (int mt = 0; mt < 2; ++mt) {
        int rl1 = wm * 32 + mt * 16 + g;
        int rl2 = rl1 + 8;
#pragma unroll
        for (int nt = 0; nt < 12; ++nt) {
            int col = wn * 96 + nt * 8 + tg * 2;
            float b0v = bias[col], b1v = bias[col + 1];
            zbuf[rl1 * 392 + col]     = fmaxf(acc[mt][nt][0] * INV_SCALE + b0v, 0.f);
            zbuf[rl1 * 392 + col + 1] = fmaxf(acc[mt][nt][1] * INV_SCALE + b1v, 0.f);
            zbuf[rl2 * 392 + col]     = fmaxf(acc[mt][nt][2] * INV_SCALE + b0v, 0.f);
            zbuf[rl2 * 392 + col + 1] = fmaxf(acc[mt][nt][3] * INV_SCALE + b1v, 0.f);
        }
    }
    __syncthreads();

#pragma unroll
    for (int u = 0; u < 8; ++u) {
        int idx = tid + 256 * u;           // 2048 float4 slots: row(0..63) x c4(0..31)
        int row = idx >> 5;
        int c4 = idx & 31;
        if (row0 + row < M) {
            const float* zr = zbuf + row * 392 + c4 * 4;
            float4 v0 = *(const float4*)zr;
            float4 v1 = *(const float4*)(zr + 128);
            float4 v2 = *(const float4*)(zr + 256);
            float4 o;
            o.x = v0.x + v1.x + v2.x;
            o.y = v0.y + v1.y + v2.y;
            o.z = v0.z + v1.z + v2.z;
            o.w = v0.w + v1.w + v2.w;
            *(float4*)(out + (size_t)(sg.rowBase + row0 + row) * FDIM + c4 * 4) = o;
        }
    }
}

// ---------------- host launch ----------------
extern "C" void kernel_launch(void* const* d_in, const int* in_sizes, int n_in,
                              void* d_out, int out_size) {
    const float* adj0 = (const float*)d_in[0];
    const float* adj1 = (const float*)d_in[1];
    const float* adj2 = (const float*)d_in[2];
    const float* h0   = (const float*)d_in[3];
    const float* h1   = (const float*)d_in[4];
    const float* h2   = (const float*)d_in[5];
    const int*   idx0 = (const int*)d_in[6];
    const int*   idx1 = (const int*)d_in[7];
    const float* Ws   = (const float*)d_in[8];
    const float* bsp  = (const float*)d_in[9];
    float* out = (float*)d_out;

    cudaFuncSetAttribute(k_gemm1, cudaFuncAttributeMaxDynamicSharedMemorySize, SMEM1_BYTES);
    cudaFuncSetAttribute(k_gemm2, cudaFuncAttributeMaxDynamicSharedMemorySize, SMEM2_BYTES);

    k_prep_h<<<1750, 256>>>(h0, h1, h2, Ws);
    k_scatter_inv<<<16, 256>>>(idx0, idx1);
    k_convert_adj<<<82032, 256>>>(adj0, adj1, adj2);

    Gemm1Cfg c1;
    c1.seg[0] = { NL0, 0,   0,       0,     0 };
    c1.seg[1] = { NL1, 125, 1024000, 49152, 3072000 };
    c1.seg[2] = { NL2, 188, 1536000, 98304, 4608000 };
    k_gemm1<<<220, 256, SMEM1_BYTES>>>(c1);

    k_gather_y<<<2625, 256>>>(idx0, idx1);

    Gemm2Cfg c2;
    c2.seg[0] = { NL0, 0,   0,          0,                       0,         0 };
    c2.seg[1] = { NL1, 125, 64000000LL, (long long)NL0 * NCOL,   NL0,       1 };
    c2.seg[2] = { NL2, 188, 80000000LL, (long long)12000 * NCOL, NL0 + NL1, 2 };
    k_gemm2<<<220, 256, SMEM2_BYTES>>>(c2, bsp, out);
}

// round 9
// speedup vs baseline: 1.4375x; 1.1128x over previous
#include <cuda_runtime.h>
#include <cuda_fp16.h>
#include <cstdint>

// Problem constants (fixed by the dataset)
#define NL0 8000
#define NL1 4000
#define NL2 2000
#define NTOT 14000
#define FDIM 128
#define NCOL 384

static constexpr float ADJ_SCALE = 4096.0f;
static constexpr float INV_SCALE = 1.0f / 4096.0f;

// ---------------- device scratch (static, no allocations) ----------------
__device__ __half g_adjh[84000000];        // adj0|adj1|adj2 in fp16, scaled
__device__ __half g_hh[NTOT * FDIM];       // h0|h1|h2 fp16
__device__ __half g_wcat[3 * FDIM * NCOL]; // per-j: [128][384] with col block i
__device__ __half g_T[NTOT * NCOL];        // T_j = h_j @ Wcat_j
__device__ __half g_Y[NTOT * NCOL];        // gathered/scattered B operand [k][384]
__device__ int    g_inv0[NL0];
__device__ int    g_inv1[NL1];

__device__ __forceinline__ void cp16(__half* dst, const void* src, bool full) {
    unsigned d = (unsigned)__cvta_generic_to_shared(dst);
    int n = full ? 16 : 0;
    asm volatile("cp.async.cg.shared.global [%0], [%1], 16, %2;\n" :: "r"(d), "l"(src), "r"(n));
}

// ---------------- prep kernels (R1-proven) ----------------
__global__ void k_prep_h(const float* __restrict__ h0, const float* __restrict__ h1,
                         const float* __restrict__ h2, const float* __restrict__ Ws) {
    int t = blockIdx.x * blockDim.x + threadIdx.x;
    if (t < 448000) {
        int e = t * 4;
        const float* src;
        if (e < 1024000) src = h0 + e;
        else if (e < 1536000) src = h1 + (e - 1024000);
        else src = h2 + (e - 1536000);
        float4 v = *(const float4*)src;
        *(__half2*)(g_hh + e)     = __floats2half2_rn(v.x, v.y);
        *(__half2*)(g_hh + e + 2) = __floats2half2_rn(v.z, v.w);
    }
    if (t < 3 * FDIM * NCOL) {
        int j = t / 49152;
        int rem = t % 49152;
        int k = rem / 384;
        int col = rem % 384;
        int i = col >> 7;
        int c = col & 127;
        g_wcat[t] = __float2half(Ws[(((size_t)(i * 3 + j) * 128) + k) * 128 + c]);
    }
    if (t < NL0) g_inv0[t] = -1;
    if (t < NL1) g_inv1[t] = -1;
}

__global__ void k_scatter_inv(const int* __restrict__ idx0, const int* __restrict__ idx1) {
    int t = blockIdx.x * blockDim.x + threadIdx.x;
    if (t < NL1) g_inv0[idx0[t]] = t;
    if (t < NL2) g_inv1[idx1[t]] = t;
}

__global__ void k_convert_adj(const float* __restrict__ a0, const float* __restrict__ a1,
                              const float* __restrict__ a2) {
    int t = blockIdx.x * blockDim.x + threadIdx.x;
    if (t >= 21000000) return;
    long long e = (long long)t * 4;
    const float* src;
    if (e < 64000000LL) src = a0 + e;
    else if (e < 80000000LL) src = a1 + (e - 64000000LL);
    else src = a2 + (e - 80000000LL);
    float4 v = *(const float4*)src;
    *(__half2*)(g_adjh + e)     = __floats2half2_rn(v.x * ADJ_SCALE, v.y * ADJ_SCALE);
    *(__half2*)(g_adjh + e + 2) = __floats2half2_rn(v.z * ADJ_SCALE, v.w * ADJ_SCALE);
}

// Gather T -> Y (one 16B chunk per thread)
__global__ void k_gather_y(const int* __restrict__ idx0, const int* __restrict__ idx1) {
    int tid = blockIdx.x * blockDim.x + threadIdx.x;
    if (tid >= NTOT * 3 * 16) return;
    int seg = tid & 15;
    int rest = tid >> 4;
    int j = rest % 3;
    int rg = rest / 3;
    int i, r;
    if (rg < NL0)            { i = 0; r = rg; }
    else if (rg < NL0 + NL1) { i = 1; r = rg - NL0; }
    else                     { i = 2; r = rg - NL0 - NL1; }
    int s = -1;
    if (i == 0) {
        if (j == 0) s = r;
        else if (j == 1) s = g_inv0[r];
        else { int t0 = g_inv0[r]; s = (t0 >= 0) ? g_inv1[t0] : -1; }
    } else if (i == 1) {
        if (j == 0) s = idx0[r];
        else if (j == 1) s = r;
        else s = g_inv1[r];
    } else {
        if (j == 0) s = idx0[idx1[r]];
        else if (j == 1) s = idx1[r];
        else s = r;
    }
    uint4 v = make_uint4(0u, 0u, 0u, 0u);
    if (s >= 0) {
        int srow = (j == 0 ? 0 : (j == 1 ? NL0 : NL0 + NL1)) + s;
        v = *(const uint4*)(g_T + (size_t)srow * NCOL + i * 128 + seg * 8);
    }
    *(uint4*)(g_Y + (size_t)rg * NCOL + j * 128 + seg * 8) = v;
}

// ---------------- shared GEMM tiling constants ----------------
#define BM 64
#define BK 32
#define APITCH 40   // halves per A smem row (pad 8)
#define BPITCH 392  // halves per B smem row (pad 8)
#define STG_HALVES (BM * APITCH + BK * BPITCH)  // 15104
#define SMEM1_BYTES (3 * STG_HALVES * 2)        // 90624
#define SMEM2_BYTES 100352                      // max(3-stage 90624, zbuf 64*392*4)

// Batched-fragment compute phase shared by both GEMMs.
// Loads all A/B fragments for one k-tile, then issues 48 MMAs back-to-back.
// bload_row/bload_col: per-thread ldmatrix.x4.trans addressing (grp = lane>>3):
//   row = (grp&1)*8 + (lane&7),  col = wn*96 + (grp>>1)*8  (+ ntp*16)
#define COMPUTE_TILE(as, bs)                                                          \
    {                                                                                 \
        uint32_t af[2][2][4];                                                         \
        uint32_t bf[2][6][4];                                                         \
        _Pragma("unroll")                                                             \
        for (int kk = 0; kk < 2; ++kk) {                                              \
            _Pragma("unroll")                                                         \
            for (int mt = 0; mt < 2; ++mt) {                                          \
                __half* p = (as) + (size_t)(wm * 32 + mt * 16 + a_row) * APITCH       \
                            + kk * 16 + a_col8;                                       \
                unsigned sp = (unsigned)__cvta_generic_to_shared(p);                  \
                asm volatile("ldmatrix.sync.aligned.m8n8.x4.shared.b16 "              \
                             "{%0,%1,%2,%3}, [%4];\n"                                 \
                             : "=r"(af[kk][mt][0]), "=r"(af[kk][mt][1]),              \
                               "=r"(af[kk][mt][2]), "=r"(af[kk][mt][3])               \
                             : "r"(sp));                                              \
            }                                                                         \
            _Pragma("unroll")                                                         \
            for (int ntp = 0; ntp < 6; ++ntp) {                                       \
                __half* p = (bs) + (size_t)(kk * 16 + bx4_row) * BPITCH               \
                            + bx4_col + ntp * 16;                                     \
                unsigned sp = (unsigned)__cvta_generic_to_shared(p);                  \
                asm volatile("ldmatrix.sync.aligned.m8n8.x4.trans.shared.b16 "        \
                             "{%0,%1,%2,%3}, [%4];\n"                                 \
                             : "=r"(bf[kk][ntp][0]), "=r"(bf[kk][ntp][1]),            \
                               "=r"(bf[kk][ntp][2]), "=r"(bf[kk][ntp][3])             \
                             : "r"(sp));                                              \
            }                                                                         \
        }                                                                             \
        _Pragma("unroll")                                                             \
        for (int kk = 0; kk < 2; ++kk) {                                              \
            _Pragma("unroll")                                                         \
            for (int ntp = 0; ntp < 6; ++ntp) {                                       \
                _Pragma("unroll")                                                     \
                for (int mt = 0; mt < 2; ++mt) {                                      \
                    asm volatile(                                                     \
                        "mma.sync.aligned.m16n8k16.row.col.f32.f16.f16.f32 "          \
                        "{%0,%1,%2,%3}, {%4,%5,%6,%7}, {%8,%9}, {%0,%1,%2,%3};\n"     \
                        : "+f"(acc[mt][2 * ntp][0]), "+f"(acc[mt][2 * ntp][1]),       \
                          "+f"(acc[mt][2 * ntp][2]), "+f"(acc[mt][2 * ntp][3])        \
                        : "r"(af[kk][mt][0]), "r"(af[kk][mt][1]),                     \
                          "r"(af[kk][mt][2]), "r"(af[kk][mt][3]),                     \
                          "r"(bf[kk][ntp][0]), "r"(bf[kk][ntp][1]));                  \
                    asm volatile(                                                     \
                        "mma.sync.aligned.m16n8k16.row.col.f32.f16.f16.f32 "          \
                        "{%0,%1,%2,%3}, {%4,%5,%6,%7}, {%8,%9}, {%0,%1,%2,%3};\n"     \
                        : "+f"(acc[mt][2 * ntp + 1][0]), "+f"(acc[mt][2 * ntp + 1][1]),\
                          "+f"(acc[mt][2 * ntp + 1][2]), "+f"(acc[mt][2 * ntp + 1][3])\
                        : "r"(af[kk][mt][0]), "r"(af[kk][mt][1]),                     \
                          "r"(af[kk][mt][2]), "r"(af[kk][mt][3]),                     \
                          "r"(bf[kk][ntp][2]), "r"(bf[kk][ntp][3]));                  \
                }                                                                     \
            }                                                                         \
        }                                                                             \
    }

// ---------------- stage-1 GEMM: T = h @ Wcat, fp16 in/out ----------------
struct Gemm1Seg { int M, tileStart; long long Aoff, Boff, Coff; };
struct Gemm1Cfg { Gemm1Seg seg[3]; };

__global__ void __launch_bounds__(256, 1) k_gemm1(Gemm1Cfg cfg) {
    extern __shared__ __align__(16) char smem_raw[];
    __half* smem = (__half*)smem_raw;

    int tid = threadIdx.x;
    int bxi = blockIdx.x;
    int s = 0;
    if (bxi >= cfg.seg[1].tileStart) s = 1;
    if (bxi >= cfg.seg[2].tileStart) s = 2;
    Gemm1Seg sg = cfg.seg[s];
    int tile = bxi - sg.tileStart;
    int row0 = tile * BM;
    int M = sg.M, K = 128;
    const __half* A = g_hh + sg.Aoff;
    const __half* B = g_wcat + sg.Boff;

    int lane = tid & 31, wid = tid >> 5;
    int wm = wid >> 2, wn = wid & 3;

    int am = tid >> 2, aseg = tid & 3;
    int br[6], bseg[6];
#pragma unroll
    for (int it = 0; it < 6; ++it) { int c = tid + it * 256; br[it] = c / 48; bseg[it] = c % 48; }

    int KT = K / BK; // 4

    auto load_tile = [&](int kt, int st) {
        __half* as = smem + st * STG_HALVES;
        __half* bs = as + BM * APITCH;
        int k0 = kt * BK;
        {
            int grow = row0 + am;
            bool p = (grow < M);
            const __half* src = p ? (A + (size_t)grow * K + k0 + aseg * 8) : A;
            cp16(as + am * APITCH + aseg * 8, src, p);
        }
#pragma unroll
        for (int it = 0; it < 6; ++it) {
            int kr = k0 + br[it];
            cp16(bs + br[it] * BPITCH + bseg[it] * 8, B + (size_t)kr * NCOL + bseg[it] * 8, true);
        }
    };

    load_tile(0, 0);
    asm volatile("cp.async.commit_group;\n");
    load_tile(1, 1);
    asm volatile("cp.async.commit_group;\n");

    float acc[2][12][4] = {};
    int a_row = lane & 15;
    int a_col8 = 8 * (lane >> 4);
    int grp = lane >> 3;
    int bx4_row = (grp & 1) * 8 + (lane & 7);
    int bx4_col = wn * 96 + (grp >> 1) * 8;

    for (int kt = 0; kt < KT; ++kt) {
        asm volatile("cp.async.wait_group 1;\n");
        __syncthreads();
        int nx = kt + 2;
        if (nx < KT) load_tile(nx, nx % 3);
        asm volatile("cp.async.commit_group;\n");

        __half* as = smem + (kt % 3) * STG_HALVES;
        __half* bs = as + BM * APITCH;
        COMPUTE_TILE(as, bs)
    }

    int g = lane >> 2, tg = lane & 3;
    __half* C = g_T + sg.Coff;
#pragma unroll
    for (int mt = 0; mt < 2; ++mt) {
        int r1 = row0 + wm * 32 + mt * 16 + g;
        int r2 = r1 + 8;
#pragma unroll
        for (int nt = 0; nt < 12; ++nt) {
            int col = wn * 96 + nt * 8 + tg * 2;
            if (r1 < M) *(__half2*)(C + (size_t)r1 * NCOL + col) =
                __floats2half2_rn(acc[mt][nt][0], acc[mt][nt][1]);
            if (r2 < M) *(__half2*)(C + (size_t)r2 * NCOL + col) =
                __floats2half2_rn(acc[mt][nt][2], acc[mt][nt][3]);
        }
    }
}

// ---------------- stage-2 GEMM (3-stage ring) + fused epilogue ----------------
struct Gemm2Seg { int M, tileStart; long long Aoff, Boff; int rowBase, lvl; };
struct Gemm2Cfg { Gemm2Seg seg[3]; };

__global__ void __launch_bounds__(256, 1) k_gemm2(Gemm2Cfg cfg,
                                                  const float* __restrict__ bsp,
                                                  float* __restrict__ out) {
    extern __shared__ __align__(16) char smem_raw[];
    __half* smem = (__half*)smem_raw;

    int tid = threadIdx.x;
    int bxi = blockIdx.x;
    int s = 0;
    if (bxi >= cfg.seg[1].tileStart) s = 1;
    if (bxi >= cfg.seg[2].tileStart) s = 2;
    Gemm2Seg sg = cfg.seg[s];
    int tile = bxi - sg.tileStart;
    int row0 = tile * BM;
    int M = sg.M, K = sg.M;          // square adj
    const __half* A = g_adjh + sg.Aoff;
    const __half* B = g_Y + sg.Boff;

    int lane = tid & 31, wid = tid >> 5;
    int wm = wid >> 2, wn = wid & 3;

    int am = tid >> 2, aseg = tid & 3;
    int br[6], bseg[6];
#pragma unroll
    for (int it = 0; it < 6; ++it) { int c = tid + it * 256; br[it] = c / 48; bseg[it] = c % 48; }

    int KT = (K + BK - 1) / BK;   // 250 / 125 / 63 (tail predicated)

    auto load_tile = [&](int kt, int st) {
        __half* as = smem + st * STG_HALVES;
        __half* bs = as + BM * APITCH;
        int k0 = kt * BK;
        {
            int grow = row0 + am;
            int gcol = k0 + aseg * 8;
            bool p = (grow < M) && (gcol < K);
            const __half* src = p ? (A + (size_t)grow * K + gcol) : A;
            cp16(as + am * APITCH + aseg * 8, src, p);
        }
#pragma unroll
        for (int it = 0; it < 6; ++it) {
            int kr = k0 + br[it];
            bool p = (kr < K);
            const __half* src = p ? (B + (size_t)kr * NCOL + bseg[it] * 8) : B;
            cp16(bs + br[it] * BPITCH + bseg[it] * 8, src, p);
        }
    };

    load_tile(0, 0);
    asm volatile("cp.async.commit_group;\n");
    load_tile(1, 1);
    asm volatile("cp.async.commit_group;\n");

    float acc[2][12][4] = {};
    int a_row = lane & 15;
    int a_col8 = 8 * (lane >> 4);
    int grp = lane >> 3;
    int bx4_row = (grp & 1) * 8 + (lane & 7);
    int bx4_col = wn * 96 + (grp >> 1) * 8;

    for (int kt = 0; kt < KT; ++kt) {
        asm volatile("cp.async.wait_group 1;\n");
        __syncthreads();
        int nx = kt + 2;
        if (nx < KT) load_tile(nx, nx % 3);
        asm volatile("cp.async.commit_group;\n");

        __half* as = smem + (kt % 3) * STG_HALVES;
        __half* bs = as + BM * APITCH;
        COMPUTE_TILE(as, bs)
    }

    // ---- fused epilogue: relu(acc*inv + b) into smem, then cross-j sum ----
    asm volatile("cp.async.wait_group 0;\n");
    __syncthreads();   // all warps done with pipeline smem

    float* zbuf = (float*)smem_raw;        // [64][392] fp32 (fits in 100352 B)
    const float* bias = bsp + sg.lvl * 3 * FDIM;  // contiguous 384 floats for this level
    int g = lane >> 2, tg = lane & 3;
#pragma unroll
    for (int mt = 0; mt < 2; ++mt) {
        int rl1 = wm * 32 + mt * 16 + g;
        int rl2 = rl1 + 8;
#pragma unroll
        for (int nt = 0; nt < 12; ++nt) {
            int col = wn * 96 + nt * 8 + tg * 2;
            float b0v = bias[col], b1v = bias[col + 1];
            zbuf[rl1 * 392 + col]     = fmaxf(acc[mt][nt][0] * INV_SCALE + b0v, 0.f);
            zbuf[rl1 * 392 + col + 1] = fmaxf(acc[mt][nt][1] * INV_SCALE + b1v, 0.f);
            zbuf[rl2 * 392 + col]     = fmaxf(acc[mt][nt][2] * INV_SCALE + b0v, 0.f);
            zbuf[rl2 * 392 + col + 1] = fmaxf(acc[mt][nt][3] * INV_SCALE + b1v, 0.f);
        }
    }
    __syncthreads();

#pragma unroll
    for (int u = 0; u < 8; ++u) {
        int idx = tid + 256 * u;           // 2048 float4 slots: row(0..63) x c4(0..31)
        int row = idx >> 5;
        int c4 = idx & 31;
        if (row0 + row < M) {
            const float* zr = zbuf + row * 392 + c4 * 4;
            float4 v0 = *(const float4*)zr;
            float4 v1 = *(const float4*)(zr + 128);
            float4 v2 = *(const float4*)(zr + 256);
            float4 o;
            o.x = v0.x + v1.x + v2.x;
            o.y = v0.y + v1.y + v2.y;
            o.z = v0.z + v1.z + v2.z;
            o.w = v0.w + v1.w + v2.w;
            *(float4*)(out + (size_t)(sg.rowBase + row0 + row) * FDIM + c4 * 4) = o;
        }
    }
}

// ---------------- host launch ----------------
extern "C" void kernel_launch(void* const* d_in, const int* in_sizes, int n_in,
                              void* d_out, int out_size) {
    const float* adj0 = (const float*)d_in[0];
    const float* adj1 = (const float*)d_in[1];
    const float* adj2 = (const float*)d_in[2];
    const float* h0   = (const float*)d_in[3];
    const float* h1   = (const float*)d_in[4];
    const float* h2   = (const float*)d_in[5];
    const int*   idx0 = (const int*)d_in[6];
    const int*   idx1 = (const int*)d_in[7];
    const float* Ws   = (const float*)d_in[8];
    const float* bsp  = (const float*)d_in[9];
    float* out = (float*)d_out;

    cudaFuncSetAttribute(k_gemm1, cudaFuncAttributeMaxDynamicSharedMemorySize, SMEM1_BYTES);
    cudaFuncSetAttribute(k_gemm2, cudaFuncAttributeMaxDynamicSharedMemorySize, SMEM2_BYTES);

    k_prep_h<<<1750, 256>>>(h0, h1, h2, Ws);
    k_scatter_inv<<<16, 256>>>(idx0, idx1);
    k_convert_adj<<<82032, 256>>>(adj0, adj1, adj2);

    Gemm1Cfg c1;
    c1.seg[0] = { NL0, 0,   0,       0,     0 };
    c1.seg[1] = { NL1, 125, 1024000, 49152, 3072000 };
    c1.seg[2] = { NL2, 188, 1536000, 98304, 4608000 };
    k_gemm1<<<220, 256, SMEM1_BYTES>>>(c1);

    k_gather_y<<<2625, 256>>>(idx0, idx1);

    Gemm2Cfg c2;
    c2.seg[0] = { NL0, 0,   0,          0,                       0,         0 };
    c2.seg[1] = { NL1, 125, 64000000LL, (long long)NL0 * NCOL,   NL0,       1 };
    c2.seg[2] = { NL2, 188, 80000000LL, (long long)12000 * NCOL, NL0 + NL1, 2 };
    k_gemm2<<<220, 256, SMEM2_BYTES>>>(c2, bsp, out);
}

// round 10
// speedup vs baseline: 1.7317x; 1.2047x over previous
#include <cuda_runtime.h>
#include <cuda_fp16.h>
#include <cstdint>

// Problem constants (fixed by the dataset)
#define NL0 8000
#define NL1 4000
#define NL2 2000
#define NTOT 14000
#define FDIM 128
#define NCOL 384

static constexpr float ADJ_SCALE = 4096.0f;
static constexpr float INV_SCALE = 1.0f / 4096.0f;

// ---------------- device scratch (static, no allocations) ----------------
__device__ __half g_hh[NTOT * FDIM];       // h0|h1|h2 fp16
__device__ __half g_wcat[3 * FDIM * NCOL]; // per-j: [128][384] with col block i
__device__ __half g_T[NTOT * NCOL];        // T_j = h_j @ Wcat_j
__device__ __half g_Y[NTOT * NCOL];        // gathered/scattered B operand [k][384]
__device__ int    g_inv0[NL0];
__device__ int    g_inv1[NL1];

__device__ __forceinline__ void cp16(const void* dst, const void* src, bool full) {
    unsigned d = (unsigned)__cvta_generic_to_shared(dst);
    int n = full ? 16 : 0;
    asm volatile("cp.async.cg.shared.global [%0], [%1], 16, %2;\n" :: "r"(d), "l"(src), "r"(n));
}

// ---------------- prep kernels (R1-proven) ----------------
__global__ void k_prep_h(const float* __restrict__ h0, const float* __restrict__ h1,
                         const float* __restrict__ h2, const float* __restrict__ Ws) {
    int t = blockIdx.x * blockDim.x + threadIdx.x;
    if (t < 448000) {
        int e = t * 4;
        const float* src;
        if (e < 1024000) src = h0 + e;
        else if (e < 1536000) src = h1 + (e - 1024000);
        else src = h2 + (e - 1536000);
        float4 v = *(const float4*)src;
        *(__half2*)(g_hh + e)     = __floats2half2_rn(v.x, v.y);
        *(__half2*)(g_hh + e + 2) = __floats2half2_rn(v.z, v.w);
    }
    if (t < 3 * FDIM * NCOL) {
        int j = t / 49152;
        int rem = t % 49152;
        int k = rem / 384;
        int col = rem % 384;
        int i = col >> 7;
        int c = col & 127;
        g_wcat[t] = __float2half(Ws[(((size_t)(i * 3 + j) * 128) + k) * 128 + c]);
    }
    if (t < NL0) g_inv0[t] = -1;
    if (t < NL1) g_inv1[t] = -1;
}

__global__ void k_scatter_inv(const int* __restrict__ idx0, const int* __restrict__ idx1) {
    int t = blockIdx.x * blockDim.x + threadIdx.x;
    if (t < NL1) g_inv0[idx0[t]] = t;
    if (t < NL2) g_inv1[idx1[t]] = t;
}

// Gather T -> Y (one 16B chunk per thread)
__global__ void k_gather_y(const int* __restrict__ idx0, const int* __restrict__ idx1) {
    int tid = blockIdx.x * blockDim.x + threadIdx.x;
    if (tid >= NTOT * 3 * 16) return;
    int seg = tid & 15;
    int rest = tid >> 4;
    int j = rest % 3;
    int rg = rest / 3;
    int i, r;
    if (rg < NL0)            { i = 0; r = rg; }
    else if (rg < NL0 + NL1) { i = 1; r = rg - NL0; }
    else                     { i = 2; r = rg - NL0 - NL1; }
    int s = -1;
    if (i == 0) {
        if (j == 0) s = r;
        else if (j == 1) s = g_inv0[r];
        else { int t0 = g_inv0[r]; s = (t0 >= 0) ? g_inv1[t0] : -1; }
    } else if (i == 1) {
        if (j == 0) s = idx0[r];
        else if (j == 1) s = r;
        else s = g_inv1[r];
    } else {
        if (j == 0) s = idx0[idx1[r]];
        else if (j == 1) s = idx1[r];
        else s = r;
    }
    uint4 v = make_uint4(0u, 0u, 0u, 0u);
    if (s >= 0) {
        int srow = (j == 0 ? 0 : (j == 1 ? NL0 : NL0 + NL1)) + s;
        v = *(const uint4*)(g_T + (size_t)srow * NCOL + i * 128 + seg * 8);
    }
    *(uint4*)(g_Y + (size_t)rg * NCOL + j * 128 + seg * 8) = v;
}

// ---------------- shared GEMM tiling constants ----------------
#define BM 64
#define BK 32
#define APITCH 40   // halves per A fp16 smem row (pad 8)
#define BPITCH 392  // halves per B smem row (pad 8)
#define STG_HALVES (BM * APITCH + BK * BPITCH)  // 15104 (gemm1 stage)
#define SMEM1_BYTES (3 * STG_HALVES * 2)        // 90624

// gemm2 stage: [A32: 64x36 fp32 = 9216][A16: 64x40 half = 5120][B: 32x392 half = 25088]
#define A32PITCH 36
#define STG2_A16_OFF 9216
#define STG2_B_OFF 14336
#define STG2_BYTES 39424
#define NSTG2 4
#define SMEM2_BYTES (NSTG2 * STG2_BYTES)        // 157696 (>= zbuf 100352)

// Batched-fragment compute phase shared by both GEMMs (R9-proven).
#define COMPUTE_TILE(as, bs)                                                          \
    {                                                                                 \
        uint32_t af[2][2][4];                                                         \
        uint32_t bf[2][6][4];                                                         \
        _Pragma("unroll")                                                             \
        for (int kk = 0; kk < 2; ++kk) {                                              \
            _Pragma("unroll")                                                         \
            for (int mt = 0; mt < 2; ++mt) {                                          \
                __half* p = (as) + (size_t)(wm * 32 + mt * 16 + a_row) * APITCH       \
                            + kk * 16 + a_col8;                                       \
                unsigned sp = (unsigned)__cvta_generic_to_shared(p);                  \
                asm volatile("ldmatrix.sync.aligned.m8n8.x4.shared.b16 "              \
                             "{%0,%1,%2,%3}, [%4];\n"                                 \
                             : "=r"(af[kk][mt][0]), "=r"(af[kk][mt][1]),              \
                               "=r"(af[kk][mt][2]), "=r"(af[kk][mt][3])               \
                             : "r"(sp));                                              \
            }                                                                         \
            _Pragma("unroll")                                                         \
            for (int ntp = 0; ntp < 6; ++ntp) {                                       \
                __half* p = (bs) + (size_t)(kk * 16 + bx4_row) * BPITCH               \
                            + bx4_col + ntp * 16;                                     \
                unsigned sp = (unsigned)__cvta_generic_to_shared(p);                  \
                asm volatile("ldmatrix.sync.aligned.m8n8.x4.trans.shared.b16 "        \
                             "{%0,%1,%2,%3}, [%4];\n"                                 \
                             : "=r"(bf[kk][ntp][0]), "=r"(bf[kk][ntp][1]),            \
                               "=r"(bf[kk][ntp][2]), "=r"(bf[kk][ntp][3])             \
                             : "r"(sp));                                              \
            }                                                                         \
        }                                                                             \
        _Pragma("unroll")                                                             \
        for (int kk = 0; kk < 2; ++kk) {                                              \
            _Pragma("unroll")                                                         \
            for (int ntp = 0; ntp < 6; ++ntp) {                                       \
                _Pragma("unroll")                                                     \
                for (int mt = 0; mt < 2; ++mt) {                                      \
                    asm volatile(                                                     \
                        "mma.sync.aligned.m16n8k16.row.col.f32.f16.f16.f32 "          \
                        "{%0,%1,%2,%3}, {%4,%5,%6,%7}, {%8,%9}, {%0,%1,%2,%3};\n"     \
                        : "+f"(acc[mt][2 * ntp][0]), "+f"(acc[mt][2 * ntp][1]),       \
                          "+f"(acc[mt][2 * ntp][2]), "+f"(acc[mt][2 * ntp][3])        \
                        : "r"(af[kk][mt][0]), "r"(af[kk][mt][1]),                     \
                          "r"(af[kk][mt][2]), "r"(af[kk][mt][3]),                     \
                          "r"(bf[kk][ntp][0]), "r"(bf[kk][ntp][1]));                  \
                    asm volatile(                                                     \
                        "mma.sync.aligned.m16n8k16.row.col.f32.f16.f16.f32 "          \
                        "{%0,%1,%2,%3}, {%4,%5,%6,%7}, {%8,%9}, {%0,%1,%2,%3};\n"     \
                        : "+f"(acc[mt][2 * ntp + 1][0]), "+f"(acc[mt][2 * ntp + 1][1]),\
                          "+f"(acc[mt][2 * ntp + 1][2]), "+f"(acc[mt][2 * ntp + 1][3])\
                        : "r"(af[kk][mt][0]), "r"(af[kk][mt][1]),                     \
                          "r"(af[kk][mt][2]), "r"(af[kk][mt][3]),                     \
                          "r"(bf[kk][ntp][2]), "r"(bf[kk][ntp][3]));                  \
                }                                                                     \
            }                                                                         \
        }                                                                             \
    }

// ---------------- stage-1 GEMM (R9-proven): T = h @ Wcat, fp16 in/out ----------------
struct Gemm1Seg { int M, tileStart; long long Aoff, Boff, Coff; };
struct Gemm1Cfg { Gemm1Seg seg[3]; };

__global__ void __launch_bounds__(256, 1) k_gemm1(Gemm1Cfg cfg) {
    extern __shared__ __align__(16) char smem_raw[];
    __half* smem = (__half*)smem_raw;

    int tid = threadIdx.x;
    int bxi = blockIdx.x;
    int s = 0;
    if (bxi >= cfg.seg[1].tileStart) s = 1;
    if (bxi >= cfg.seg[2].tileStart) s = 2;
    Gemm1Seg sg = cfg.seg[s];
    int tile = bxi - sg.tileStart;
    int row0 = tile * BM;
    int M = sg.M, K = 128;
    const __half* A = g_hh + sg.Aoff;
    const __half* B = g_wcat + sg.Boff;

    int lane = tid & 31, wid = tid >> 5;
    int wm = wid >> 2, wn = wid & 3;

    int am = tid >> 2, aseg = tid & 3;
    int br[6], bseg[6];
#pragma unroll
    for (int it = 0; it < 6; ++it) { int c = tid + it * 256; br[it] = c / 48; bseg[it] = c % 48; }

    int KT = K / BK; // 4

    auto load_tile = [&](int kt, int st) {
        __half* as = smem + st * STG_HALVES;
        __half* bs = as + BM * APITCH;
        int k0 = kt * BK;
        {
            int grow = row0 + am;
            bool p = (grow < M);
            const __half* src = p ? (A + (size_t)grow * K + k0 + aseg * 8) : A;
            cp16(as + am * APITCH + aseg * 8, src, p);
        }
#pragma unroll
        for (int it = 0; it < 6; ++it) {
            int kr = k0 + br[it];
            cp16(bs + br[it] * BPITCH + bseg[it] * 8, B + (size_t)kr * NCOL + bseg[it] * 8, true);
        }
    };

    load_tile(0, 0);
    asm volatile("cp.async.commit_group;\n");
    load_tile(1, 1);
    asm volatile("cp.async.commit_group;\n");

    float acc[2][12][4] = {};
    int a_row = lane & 15;
    int a_col8 = 8 * (lane >> 4);
    int grp = lane >> 3;
    int bx4_row = (grp & 1) * 8 + (lane & 7);
    int bx4_col = wn * 96 + (grp >> 1) * 8;

    for (int kt = 0; kt < KT; ++kt) {
        asm volatile("cp.async.wait_group 1;\n");
        __syncthreads();
        int nx = kt + 2;
        if (nx < KT) load_tile(nx, nx % 3);
        asm volatile("cp.async.commit_group;\n");

        __half* as = smem + (kt % 3) * STG_HALVES;
        __half* bs = as + BM * APITCH;
        COMPUTE_TILE(as, bs)
    }

    int g = lane >> 2, tg = lane & 3;
    __half* C = g_T + sg.Coff;
#pragma unroll
    for (int mt = 0; mt < 2; ++mt) {
        int r1 = row0 + wm * 32 + mt * 16 + g;
        int r2 = r1 + 8;
#pragma unroll
        for (int nt = 0; nt < 12; ++nt) {
            int col = wn * 96 + nt * 8 + tg * 2;
            if (r1 < M) *(__half2*)(C + (size_t)r1 * NCOL + col) =
                __floats2half2_rn(acc[mt][nt][0], acc[mt][nt][1]);
            if (r2 < M) *(__half2*)(C + (size_t)r2 * NCOL + col) =
                __floats2half2_rn(acc[mt][nt][2], acc[mt][nt][3]);
        }
    }
}

// ---------------- stage-2 GEMM: fused fp32->fp16 A-convert via smem staging ----------------
// A: fp32 adj via cp.async into A32 stage, converted (x4096) smem->smem one tile ahead.
// 4-stage ring, one commit + one barrier per iter. Fused relu/bias/sum epilogue.
struct Gemm2Seg { const float* A; int M, tileStart; long long Boff; int rowBase, lvl; };
struct Gemm2Cfg { Gemm2Seg seg[3]; };

__global__ void __launch_bounds__(256, 1) k_gemm2(Gemm2Cfg cfg,
                                                  const float* __restrict__ bsp,
                                                  float* __restrict__ out) {
    extern __shared__ __align__(16) char smem_raw[];

    int tid = threadIdx.x;
    int bxi = blockIdx.x;
    int s = 0;
    if (bxi >= cfg.seg[1].tileStart) s = 1;
    if (bxi >= cfg.seg[2].tileStart) s = 2;
    Gemm2Seg sg = cfg.seg[s];
    int tile = bxi - sg.tileStart;
    int row0 = tile * BM;
    int M = sg.M, K = sg.M;          // square adj
    const float* A = sg.A;
    const __half* B = g_Y + sg.Boff;

    int lane = tid & 31, wid = tid >> 5;
    int wm = wid >> 2, wn = wid & 3;

    int am = tid >> 2, aseg = tid & 3;       // A32: row 0..63, 2x16B chunks
    int br[6], bseg[6];
#pragma unroll
    for (int it = 0; it < 6; ++it) { int c = tid + it * 256; br[it] = c / 48; bseg[it] = c % 48; }

    int KT = (K + BK - 1) / BK;   // 250 / 125 / 63 (tail zero-filled)

    auto A32p = [&](int st) { return (float*)(smem_raw + st * STG2_BYTES); };
    auto A16p = [&](int st) { return (__half*)(smem_raw + st * STG2_BYTES + STG2_A16_OFF); };
    auto Bp   = [&](int st) { return (__half*)(smem_raw + st * STG2_BYTES + STG2_B_OFF); };

    auto load_tile = [&](int kt, int st) {
        int k0 = kt * BK;
        {
            int grow = row0 + am;
            int gc1 = k0 + aseg * 8;
            int gc2 = gc1 + 4;
            bool rowok = (grow < M);
            bool p1 = rowok && (gc1 < K);   // K % 4 == 0, chunk-start test exact
            bool p2 = rowok && (gc2 < K);
            const float* base = A + (size_t)grow * K;
            float* d = A32p(st) + am * A32PITCH + aseg * 8;
            cp16(d,     p1 ? (base + gc1) : A, p1);
            cp16(d + 4, p2 ? (base + gc2) : A, p2);
        }
        __half* bs = Bp(st);
#pragma unroll
        for (int it = 0; it < 6; ++it) {
            int kr = k0 + br[it];
            bool p = (kr < K);
            const __half* src = p ? (B + (size_t)kr * NCOL + bseg[it] * 8) : B;
            cp16(bs + br[it] * BPITCH + bseg[it] * 8, src, p);
        }
    };

    // smem fp32 -> smem fp16 (x ADJ_SCALE), 8 floats per thread
    auto convert = [&](int st) {
        int row = tid >> 2, c8 = tid & 3;
        const float* src = A32p(st) + row * A32PITCH + c8 * 8;
        float4 v0 = *(const float4*)src;
        float4 v1 = *(const float4*)(src + 4);
        uint4 p;
        *(__half2*)&p.x = __floats2half2_rn(v0.x * ADJ_SCALE, v0.y * ADJ_SCALE);
        *(__half2*)&p.y = __floats2half2_rn(v0.z * ADJ_SCALE, v0.w * ADJ_SCALE);
        *(__half2*)&p.z = __floats2half2_rn(v1.x * ADJ_SCALE, v1.y * ADJ_SCALE);
        *(__half2*)&p.w = __floats2half2_rn(v1.z * ADJ_SCALE, v1.w * ADJ_SCALE);
        *(uint4*)(A16p(st) + row * APITCH + c8 * 8) = p;
    };

    // prologue: fill 3 of 4 stages; convert tile 0
    load_tile(0, 0);
    asm volatile("cp.async.commit_group;\n");
    load_tile(1, 1);
    asm volatile("cp.async.commit_group;\n");
    load_tile(2, 2);
    asm volatile("cp.async.commit_group;\n");
    asm volatile("cp.async.wait_group 2;\n");   // tile 0 landed
    __syncthreads();
    convert(0);

    float acc[2][12][4] = {};
    int a_row = lane & 15;
    int a_col8 = 8 * (lane >> 4);
    int grp = lane >> 3;
    int bx4_row = (grp & 1) * 8 + (lane & 7);
    int bx4_col = wn * 96 + (grp >> 1) * 8;

    for (int kt = 0; kt < KT; ++kt) {
        asm volatile("cp.async.wait_group 1;\n");   // tile kt+1 landed
        __syncthreads();                            // convert(kt) visible; stage reuse safe
        if (kt + 1 < KT) convert((kt + 1) & 3);     // convert next tile (independent of compute)
        __half* as = A16p(kt & 3);
        __half* bs = Bp(kt & 3);
        COMPUTE_TILE(as, bs)
        int nx = kt + 3;
        if (nx < KT) load_tile(nx, nx & 3);
        asm volatile("cp.async.commit_group;\n");
    }

    // ---- fused epilogue: relu(acc*inv + b) into smem, then cross-j sum ----
    asm volatile("cp.async.wait_group 0;\n");
    __syncthreads();   // all warps done with pipeline smem

    float* zbuf = (float*)smem_raw;        // [64][392] fp32 (fits in 157696 B)
    const float* bias = bsp + sg.lvl * 3 * FDIM;
    int g = lane >> 2, tg = lane & 3;
#pragma unroll
    for (int mt = 0; mt < 2; ++mt) {
        int rl1 = wm * 32 + mt * 16 + g;
        int rl2 = rl1 + 8;
#pragma unroll
        for (int nt = 0; nt < 12; ++nt) {
            int col = wn * 96 + nt * 8 + tg * 2;
            float b0v = bias[col], b1v = bias[col + 1];
            zbuf[rl1 * 392 + col]     = fmaxf(acc[mt][nt][0] * INV_SCALE + b0v, 0.f);
            zbuf[rl1 * 392 + col + 1] = fmaxf(acc[mt][nt][1] * INV_SCALE + b1v, 0.f);
            zbuf[rl2 * 392 + col]     = fmaxf(acc[mt][nt][2] * INV_SCALE + b0v, 0.f);
            zbuf[rl2 * 392 + col + 1] = fmaxf(acc[mt][nt][3] * INV_SCALE + b1v, 0.f);
        }
    }
    __syncthreads();

#pragma unroll
    for (int u = 0; u < 8; ++u) {
        int idx = tid + 256 * u;           // 2048 float4 slots: row(0..63) x c4(0..31)
        int row = idx >> 5;
        int c4 = idx & 31;
        if (row0 + row < M) {
            const float* zr = zbuf + row * 392 + c4 * 4;
            float4 v0 = *(const float4*)zr;
            float4 v1 = *(const float4*)(zr + 128);
            float4 v2 = *(const float4*)(zr + 256);
            float4 o;
            o.x = v0.x + v1.x + v2.x;
            o.y = v0.y + v1.y + v2.y;
            o.z = v0.z + v1.z + v2.z;
            o.w = v0.w + v1.w + v2.w;
            *(float4*)(out + (size_t)(sg.rowBase + row0 + row) * FDIM + c4 * 4) = o;
        }
    }
}

// ---------------- host launch ----------------
extern "C" void kernel_launch(void* const* d_in, const int* in_sizes, int n_in,
                              void* d_out, int out_size) {
    const float* adj0 = (const float*)d_in[0];
    const float* adj1 = (const float*)d_in[1];
    const float* adj2 = (const float*)d_in[2];
    const float* h0   = (const float*)d_in[3];
    const float* h1   = (const float*)d_in[4];
    const float* h2   = (const float*)d_in[5];
    const int*   idx0 = (const int*)d_in[6];
    const int*   idx1 = (const int*)d_in[7];
    const float* Ws   = (const float*)d_in[8];
    const float* bsp  = (const float*)d_in[9];
    float* out = (float*)d_out;

    cudaFuncSetAttribute(k_gemm1, cudaFuncAttributeMaxDynamicSharedMemorySize, SMEM1_BYTES);
    cudaFuncSetAttribute(k_gemm2, cudaFuncAttributeMaxDynamicSharedMemorySize, SMEM2_BYTES);

    k_prep_h<<<1750, 256>>>(h0, h1, h2, Ws);
    k_scatter_inv<<<16, 256>>>(idx0, idx1);

    Gemm1Cfg c1;
    c1.seg[0] = { NL0, 0,   0,       0,     0 };
    c1.seg[1] = { NL1, 125, 1024000, 49152, 3072000 };
    c1.seg[2] = { NL2, 188, 1536000, 98304, 4608000 };
    k_gemm1<<<220, 256, SMEM1_BYTES>>>(c1);

    k_gather_y<<<2625, 256>>>(idx0, idx1);

    Gemm2Cfg c2;
    c2.seg[0] = { adj0, NL0, 0,   0,                       0,         0 };
    c2.seg[1] = { adj1, NL1, 125, (long long)NL0 * NCOL,   NL0,       1 };
    c2.seg[2] = { adj2, NL2, 188, (long long)12000 * NCOL, NL0 + NL1, 2 };
    k_gemm2<<<220, 256, SMEM2_BYTES>>>(c2, bsp, out);
}

// round 12
// speedup vs baseline: 1.8951x; 1.0944x over previous
#include <cuda_runtime.h>
#include <cuda_fp16.h>
#include <cstdint>

// Problem constants (fixed by the dataset)
#define NL0 8000
#define NL1 4000
#define NL2 2000
#define NTOT 14000
#define FDIM 128
#define NCOL 384

static constexpr float ADJ_SCALE = 4096.0f;
static constexpr float INV_SCALE = 1.0f / 4096.0f;

// ---------------- device scratch (static, no allocations) ----------------
__device__ __half g_hh[NTOT * FDIM];       // h0|h1|h2 fp16
__device__ __half g_wcat[3 * FDIM * NCOL]; // per-j: [128][384] with col block i
__device__ __half g_T[NTOT * NCOL];        // T_j = h_j @ Wcat_j
__device__ __half g_Y[NTOT * NCOL];        // gathered/scattered B operand [k][384]
__device__ float  g_Z[NTOT * NCOL];        // split-K accumulation target
__device__ int    g_inv0[NL0];
__device__ int    g_inv1[NL1];

__device__ __forceinline__ void cp16(const void* dst, const void* src, bool full) {
    unsigned d = (unsigned)__cvta_generic_to_shared(dst);
    int n = full ? 16 : 0;
    asm volatile("cp.async.cg.shared.global [%0], [%1], 16, %2;\n" :: "r"(d), "l"(src), "r"(n));
}

// Dummy first launch: shifts k_gemm2 to launch #6 so ncu (-s 5 -c 1) captures it.
__global__ void k_dummy() {}

// ---------------- prep kernels ----------------
__global__ void k_prep_h(const float* __restrict__ h0, const float* __restrict__ h1,
                         const float* __restrict__ h2, const float* __restrict__ Ws) {
    int t = blockIdx.x * blockDim.x + threadIdx.x;
    if (t < 448000) {
        int e = t * 4;
        const float* src;
        if (e < 1024000) src = h0 + e;
        else if (e < 1536000) src = h1 + (e - 1024000);
        else src = h2 + (e - 1536000);
        float4 v = *(const float4*)src;
        *(__half2*)(g_hh + e)     = __floats2half2_rn(v.x, v.y);
        *(__half2*)(g_hh + e + 2) = __floats2half2_rn(v.z, v.w);
    }
    if (t < 3 * FDIM * NCOL) {
        int j = t / 49152;
        int rem = t % 49152;
        int k = rem / 384;
        int col = rem % 384;
        int i = col >> 7;
        int c = col & 127;
        g_wcat[t] = __float2half(Ws[(((size_t)(i * 3 + j) * 128) + k) * 128 + c]);
    }
    if (t < (NTOT * NCOL) / 4) {
        ((float4*)g_Z)[t] = make_float4(0.f, 0.f, 0.f, 0.f);
    }
    if (t < NL0) g_inv0[t] = -1;
    if (t < NL1) g_inv1[t] = -1;
}

__global__ void k_scatter_inv(const int* __restrict__ idx0, const int* __restrict__ idx1) {
    int t = blockIdx.x * blockDim.x + threadIdx.x;
    if (t < NL1) g_inv0[idx0[t]] = t;
    if (t < NL2) g_inv1[idx1[t]] = t;
}

// Gather T -> Y (one 16B chunk per thread)
__global__ void k_gather_y(const int* __restrict__ idx0, const int* __restrict__ idx1) {
    int tid = blockIdx.x * blockDim.x + threadIdx.x;
    if (tid >= NTOT * 3 * 16) return;
    int seg = tid & 15;
    int rest = tid >> 4;
    int j = rest % 3;
    int rg = rest / 3;
    int i, r;
    if (rg < NL0)            { i = 0; r = rg; }
    else if (rg < NL0 + NL1) { i = 1; r = rg - NL0; }
    else                     { i = 2; r = rg - NL0 - NL1; }
    int s = -1;
    if (i == 0) {
        if (j == 0) s = r;
        else if (j == 1) s = g_inv0[r];
        else { int t0 = g_inv0[r]; s = (t0 >= 0) ? g_inv1[t0] : -1; }
    } else if (i == 1) {
        if (j == 0) s = idx0[r];
        else if (j == 1) s = r;
        else s = g_inv1[r];
    } else {
        if (j == 0) s = idx0[idx1[r]];
        else if (j == 1) s = idx1[r];
        else s = r;
    }
    uint4 v = make_uint4(0u, 0u, 0u, 0u);
    if (s >= 0) {
        int srow = (j == 0 ? 0 : (j == 1 ? NL0 : NL0 + NL1)) + s;
        v = *(const uint4*)(g_T + (size_t)srow * NCOL + i * 128 + seg * 8);
    }
    *(uint4*)(g_Y + (size_t)rg * NCOL + j * 128 + seg * 8) = v;
}

// ---------------- shared GEMM tiling constants ----------------
#define BM 64
#define BK 32
#define APITCH 40   // halves per A fp16 smem row (pad 8)
#define BPITCH 392  // halves per B smem row (pad 8)
#define STG_HALVES (BM * APITCH + BK * BPITCH)  // 15104 (gemm1 stage)
#define SMEM1_BYTES (3 * STG_HALVES * 2)        // 90624

// gemm2 stage: [A32: 64x36 fp32 = 9216][A16: 64x40 half = 5120][B: 32x392 half = 25088]
#define A32PITCH 36
#define STG2_A16_OFF 9216
#define STG2_B_OFF 14336
#define STG2_BYTES 39424
#define NSTG2 4
#define SMEM2_BYTES (NSTG2 * STG2_BYTES)        // 157696

// Batched-fragment compute phase shared by both GEMMs (R9-proven).
#define COMPUTE_TILE(as, bs)                                                          \
    {                                                                                 \
        uint32_t af[2][2][4];                                                         \
        uint32_t bf[2][6][4];                                                         \
        _Pragma("unroll")                                                             \
        for (int kk = 0; kk < 2; ++kk) {                                              \
            _Pragma("unroll")                                                         \
            for (int mt = 0; mt < 2; ++mt) {                                          \
                __half* p = (as) + (size_t)(wm * 32 + mt * 16 + a_row) * APITCH       \
                            + kk * 16 + a_col8;                                       \
                unsigned sp = (unsigned)__cvta_generic_to_shared(p);                  \
                asm volatile("ldmatrix.sync.aligned.m8n8.x4.shared.b16 "              \
                             "{%0,%1,%2,%3}, [%4];\n"                                 \
                             : "=r"(af[kk][mt][0]), "=r"(af[kk][mt][1]),              \
                               "=r"(af[kk][mt][2]), "=r"(af[kk][mt][3])               \
                             : "r"(sp));                                              \
            }                                                                         \
            _Pragma("unroll")                                                         \
            for (int ntp = 0; ntp < 6; ++ntp) {                                       \
                __half* p = (bs) + (size_t)(kk * 16 + bx4_row) * BPITCH               \
                            + bx4_col + ntp * 16;                                     \
                unsigned sp = (unsigned)__cvta_generic_to_shared(p);                  \
                asm volatile("ldmatrix.sync.aligned.m8n8.x4.trans.shared.b16 "        \
                             "{%0,%1,%2,%3}, [%4];\n"                                 \
                             : "=r"(bf[kk][ntp][0]), "=r"(bf[kk][ntp][1]),            \
                               "=r"(bf[kk][ntp][2]), "=r"(bf[kk][ntp][3])             \
                             : "r"(sp));                                              \
            }                                                                         \
        }                                                                             \
        _Pragma("unroll")                                                             \
        for (int kk = 0; kk < 2; ++kk) {                                              \
            _Pragma("unroll")                                                         \
            for (int ntp = 0; ntp < 6; ++ntp) {                                       \
                _Pragma("unroll")                                                     \
                for (int mt = 0; mt < 2; ++mt) {                                      \
                    asm volatile(                                                     \
                        "mma.sync.aligned.m16n8k16.row.col.f32.f16.f16.f32 "          \
                        "{%0,%1,%2,%3}, {%4,%5,%6,%7}, {%8,%9}, {%0,%1,%2,%3};\n"     \
                        : "+f"(acc[mt][2 * ntp][0]), "+f"(acc[mt][2 * ntp][1]),       \
                          "+f"(acc[mt][2 * ntp][2]), "+f"(acc[mt][2 * ntp][3])        \
                        : "r"(af[kk][mt][0]), "r"(af[kk][mt][1]),                     \
                          "r"(af[kk][mt][2]), "r"(af[kk][mt][3]),                     \
                          "r"(bf[kk][ntp][0]), "r"(bf[kk][ntp][1]));                  \
                    asm volatile(                                                     \
                        "mma.sync.aligned.m16n8k16.row.col.f32.f16.f16.f32 "          \
                        "{%0,%1,%2,%3}, {%4,%5,%6,%7}, {%8,%9}, {%0,%1,%2,%3};\n"     \
                        : "+f"(acc[mt][2 * ntp + 1][0]), "+f"(acc[mt][2 * ntp + 1][1]),\
                          "+f"(acc[mt][2 * ntp + 1][2]), "+f"(acc[mt][2 * ntp + 1][3])\
                        : "r"(af[kk][mt][0]), "r"(af[kk][mt][1]),                     \
                          "r"(af[kk][mt][2]), "r"(af[kk][mt][3]),                     \
                          "r"(bf[kk][ntp][2]), "r"(bf[kk][ntp][3]));                  \
                }                                                                     \
            }                                                                         \
        }                                                                             \
    }

// ---------------- stage-1 GEMM (R9-proven): T = h @ Wcat, fp16 in/out ----------------
struct Gemm1Seg { int M, tileStart; long long Aoff, Boff, Coff; };
struct Gemm1Cfg { Gemm1Seg seg[3]; };

__global__ void __launch_bounds__(256, 1) k_gemm1(Gemm1Cfg cfg) {
    extern __shared__ __align__(16) char smem_raw[];
    __half* smem = (__half*)smem_raw;

    int tid = threadIdx.x;
    int bxi = blockIdx.x;
    int s = 0;
    if (bxi >= cfg.seg[1].tileStart) s = 1;
    if (bxi >= cfg.seg[2].tileStart) s = 2;
    Gemm1Seg sg = cfg.seg[s];
    int tile = bxi - sg.tileStart;
    int row0 = tile * BM;
    int M = sg.M, K = 128;
    const __half* A = g_hh + sg.Aoff;
    const __half* B = g_wcat + sg.Boff;

    int lane = tid & 31, wid = tid >> 5;
    int wm = wid >> 2, wn = wid & 3;

    int am = tid >> 2, aseg = tid & 3;
    int br[6], bseg[6];
#pragma unroll
    for (int it = 0; it < 6; ++it) { int c = tid + it * 256; br[it] = c / 48; bseg[it] = c % 48; }

    int KT = K / BK; // 4

    auto load_tile = [&](int kt, int st) {
        __half* as = smem + st * STG_HALVES;
        __half* bs = as + BM * APITCH;
        int k0 = kt * BK;
        {
            int grow = row0 + am;
            bool p = (grow < M);
            const __half* src = p ? (A + (size_t)grow * K + k0 + aseg * 8) : A;
            cp16(as + am * APITCH + aseg * 8, src, p);
        }
#pragma unroll
        for (int it = 0; it < 6; ++it) {
            int kr = k0 + br[it];
            cp16(bs + br[it] * BPITCH + bseg[it] * 8, B + (size_t)kr * NCOL + bseg[it] * 8, true);
        }
    };

    load_tile(0, 0);
    asm volatile("cp.async.commit_group;\n");
    load_tile(1, 1);
    asm volatile("cp.async.commit_group;\n");

    float acc[2][12][4] = {};
    int a_row = lane & 15;
    int a_col8 = 8 * (lane >> 4);
    int grp = lane >> 3;
    int bx4_row = (grp & 1) * 8 + (lane & 7);
    int bx4_col = wn * 96 + (grp >> 1) * 8;

    for (int kt = 0; kt < KT; ++kt) {
        asm volatile("cp.async.wait_group 1;\n");
        __syncthreads();
        int nx = kt + 2;
        if (nx < KT) load_tile(nx, nx % 3);
        asm volatile("cp.async.commit_group;\n");

        __half* as = smem + (kt % 3) * STG_HALVES;
        __half* bs = as + BM * APITCH;
        COMPUTE_TILE(as, bs)
    }

    int g = lane >> 2, tg = lane & 3;
    __half* C = g_T + sg.Coff;
#pragma unroll
    for (int mt = 0; mt < 2; ++mt) {
        int r1 = row0 + wm * 32 + mt * 16 + g;
        int r2 = r1 + 8;
#pragma unroll
        for (int nt = 0; nt < 12; ++nt) {
            int col = wn * 96 + nt * 8 + tg * 2;
            if (r1 < M) *(__half2*)(C + (size_t)r1 * NCOL + col) =
                __floats2half2_rn(acc[mt][nt][0], acc[mt][nt][1]);
            if (r2 < M) *(__half2*)(C + (size_t)r2 * NCOL + col) =
                __floats2half2_rn(acc[mt][nt][2], acc[mt][nt][3]);
        }
    }
}

// ---------------- stage-2 GEMM: split-K pieces, fused A-convert, atomic Z ----------------
// Piece map (grid 408), big pieces first for work-stealing balance:
//   bx   0..249: L0  tile=bx>>1, half=bx&1, K-range half? [4000,8000) : [0,4000)   (125 it)
//   bx 250..375: L1  idx=bx-250, tile=idx>>1, half: [0,2016) / [2016,4000)         (63/62 it)
//   bx 376..407: L2  tile=bx-376, [0,2000)                                         (63 it)
// Each piece atomicAdds its partial 64x384 into g_Z. Max 2 contributors per element
// -> fp32 commutative -> bitwise deterministic.
__global__ void __launch_bounds__(256, 1) k_gemm2(const float* __restrict__ adj0,
                                                  const float* __restrict__ adj1,
                                                  const float* __restrict__ adj2) {
    extern __shared__ __align__(16) char smem_raw[];

    int tid = threadIdx.x;
    int bxi = blockIdx.x;

    const float* A;
    int M, K, rowBase, row0, kbeg, kend;
    if (bxi < 250) {
        A = adj0; M = NL0; K = NL0; rowBase = 0;
        row0 = (bxi >> 1) * BM;
        kbeg = (bxi & 1) ? 4000 : 0;
        kend = (bxi & 1) ? 8000 : 4000;
    } else if (bxi < 376) {
        int idx = bxi - 250;
        A = adj1; M = NL1; K = NL1; rowBase = NL0;
        row0 = (idx >> 1) * BM;
        kbeg = (idx & 1) ? 2016 : 0;
        kend = (idx & 1) ? 4000 : 2016;
    } else {
        A = adj2; M = NL2; K = NL2; rowBase = NL0 + NL1;
        row0 = (bxi - 376) * BM;
        kbeg = 0; kend = 2000;
    }
    const __half* B = g_Y + (size_t)rowBase * NCOL;

    int lane = tid & 31, wid = tid >> 5;
    int wm = wid >> 2, wn = wid & 3;

    int am = tid >> 2, aseg = tid & 3;       // A32: row 0..63, 2x16B chunks
    int br[6], bseg[6];
#pragma unroll
    for (int it = 0; it < 6; ++it) { int c = tid + it * 256; br[it] = c / 48; bseg[it] = c % 48; }

    int KT = (kend - kbeg + BK - 1) / BK;

    auto A32p = [&](int st) { return (float*)(smem_raw + st * STG2_BYTES); };
    auto A16p = [&](int st) { return (__half*)(smem_raw + st * STG2_BYTES + STG2_A16_OFF); };
    auto Bp   = [&](int st) { return (__half*)(smem_raw + st * STG2_BYTES + STG2_B_OFF); };

    auto load_tile = [&](int kt, int st) {
        int k0 = kbeg + kt * BK;
        {
            int grow = row0 + am;
            int gc1 = k0 + aseg * 8;
            int gc2 = gc1 + 4;
            bool rowok = (grow < M);
            bool p1 = rowok && (gc1 < kend);
            bool p2 = rowok && (gc2 < kend);
            const float* base = A + (size_t)grow * K;
            float* d = A32p(st) + am * A32PITCH + aseg * 8;
            cp16(d,     p1 ? (base + gc1) : A, p1);
            cp16(d + 4, p2 ? (base + gc2) : A, p2);
        }
        __half* bs = Bp(st);
#pragma unroll
        for (int it = 0; it < 6; ++it) {
            int kr = k0 + br[it];
            bool p = (kr < kend);
            const __half* src = p ? (B + (size_t)kr * NCOL + bseg[it] * 8) : B;
            cp16(bs + br[it] * BPITCH + bseg[it] * 8, src, p);
        }
    };

    // smem fp32 -> smem fp16 (x ADJ_SCALE), 8 floats per thread
    auto convert = [&](int st) {
        int row = tid >> 2, c8 = tid & 3;
        const float* src = A32p(st) + row * A32PITCH + c8 * 8;
        float4 v0 = *(const float4*)src;
        float4 v1 = *(const float4*)(src + 4);
        uint4 p;
        *(__half2*)&p.x = __floats2half2_rn(v0.x * ADJ_SCALE, v0.y * ADJ_SCALE);
        *(__half2*)&p.y = __floats2half2_rn(v0.z * ADJ_SCALE, v0.w * ADJ_SCALE);
        *(__half2*)&p.z = __floats2half2_rn(v1.x * ADJ_SCALE, v1.y * ADJ_SCALE);
        *(__half2*)&p.w = __floats2half2_rn(v1.z * ADJ_SCALE, v1.w * ADJ_SCALE);
        *(uint4*)(A16p(st) + row * APITCH + c8 * 8) = p;
    };

    // prologue: fill 3 of 4 stages; convert tile 0
    load_tile(0, 0);
    asm volatile("cp.async.commit_group;\n");
    load_tile(1, 1);
    asm volatile("cp.async.commit_group;\n");
    load_tile(2, 2);
    asm volatile("cp.async.commit_group;\n");
    asm volatile("cp.async.wait_group 2;\n");   // tile 0 landed
    __syncthreads();
    convert(0);

    float acc[2][12][4] = {};
    int a_row = lane & 15;
    int a_col8 = 8 * (lane >> 4);
    int grp = lane >> 3;
    int bx4_row = (grp & 1) * 8 + (lane & 7);
    int bx4_col = wn * 96 + (grp >> 1) * 8;

    for (int kt = 0; kt < KT; ++kt) {
        asm volatile("cp.async.wait_group 1;\n");   // tile kt+1 landed
        __syncthreads();                            // convert(kt) visible; stage reuse safe
        if (kt + 1 < KT) convert((kt + 1) & 3);     // convert next tile
        __half* as = A16p(kt & 3);
        __half* bs = Bp(kt & 3);
        COMPUTE_TILE(as, bs)
        int nx = kt + 3;
        if (nx < KT) load_tile(nx, nx & 3);
        asm volatile("cp.async.commit_group;\n");
    }

    asm volatile("cp.async.wait_group 0;\n");
    __syncthreads();

    // partial accumulation into g_Z (raw scaled values)
    float* Zb = g_Z + (size_t)(rowBase + row0) * NCOL;
    int g = lane >> 2, tg = lane & 3;
#pragma unroll
    for (int mt = 0; mt < 2; ++mt) {
        int r1 = wm * 32 + mt * 16 + g;
        int r2 = r1 + 8;
        bool p1 = (row0 + r1) < M;
        bool p2 = (row0 + r2) < M;
#pragma unroll
        for (int nt = 0; nt < 12; ++nt) {
            int col = wn * 96 + nt * 8 + tg * 2;
            if (p1) {
                atomicAdd(Zb + (size_t)r1 * NCOL + col,     acc[mt][nt][0]);
                atomicAdd(Zb + (size_t)r1 * NCOL + col + 1, acc[mt][nt][1]);
            }
            if (p2) {
                atomicAdd(Zb + (size_t)r2 * NCOL + col,     acc[mt][nt][2]);
                atomicAdd(Zb + (size_t)r2 * NCOL + col + 1, acc[mt][nt][3]);
            }
        }
    }
}

// ---------------- final epilogue: out = sum_j relu(Z_block_j * inv_scale + b) ----------------
__global__ void k_final(const float* __restrict__ bs, float* __restrict__ out) {
    int tid = blockIdx.x * blockDim.x + threadIdx.x;
    if (tid >= NTOT * FDIM) return;
    int r = tid >> 7;
    int c = tid & 127;
    int i = (r < NL0) ? 0 : ((r < NL0 + NL1) ? 1 : 2);
    float acc = 0.0f;
#pragma unroll
    for (int j = 0; j < 3; ++j) {
        float z = g_Z[(size_t)r * NCOL + j * 128 + c] * INV_SCALE + bs[(i * 3 + j) * 128 + c];
        acc += fmaxf(z, 0.0f);
    }
    out[tid] = acc;
}

// ---------------- host launch ----------------
extern "C" void kernel_launch(void* const* d_in, const int* in_sizes, int n_in,
                              void* d_out, int out_size) {
    const float* adj0 = (const float*)d_in[0];
    const float* adj1 = (const float*)d_in[1];
    const float* adj2 = (const float*)d_in[2];
    const float* h0   = (const float*)d_in[3];
    const float* h1   = (const float*)d_in[4];
    const float* h2   = (const float*)d_in[5];
    const int*   idx0 = (const int*)d_in[6];
    const int*   idx1 = (const int*)d_in[7];
    const float* Ws   = (const float*)d_in[8];
    const float* bsp  = (const float*)d_in[9];
    float* out = (float*)d_out;

    cudaFuncSetAttribute(k_gemm1, cudaFuncAttributeMaxDynamicSharedMemorySize, SMEM1_BYTES);
    cudaFuncSetAttribute(k_gemm2, cudaFuncAttributeMaxDynamicSharedMemorySize, SMEM2_BYTES);

    k_dummy<<<1, 32>>>();   // launch #1: shifts k_gemm2 to #6 for ncu -s 5 -c 1

    k_prep_h<<<5250, 256>>>(h0, h1, h2, Ws);       // #2 (also zeroes g_Z)
    k_scatter_inv<<<16, 256>>>(idx0, idx1);        // #3

    Gemm1Cfg c1;
    c1.seg[0] = { NL0, 0,   0,       0,     0 };
    c1.seg[1] = { NL1, 125, 1024000, 49152, 3072000 };
    c1.seg[2] = { NL2, 188, 1536000, 98304, 4608000 };
    k_gemm1<<<220, 256, SMEM1_BYTES>>>(c1);        // #4

    k_gather_y<<<2625, 256>>>(idx0, idx1);         // #5

    k_gemm2<<<408, 256, SMEM2_BYTES>>>(adj0, adj1, adj2);  // #6 (ncu target)

    k_final<<<7000, 256>>>(bsp, out);              // #7
}

// round 14
// speedup vs baseline: 1.9797x; 1.0446x over previous
#include <cuda_runtime.h>
#include <cuda_fp16.h>
#include <cstdint>

// Problem constants (fixed by the dataset)
#define NL0 8000
#define NL1 4000
#define NL2 2000
#define NTOT 14000
#define FDIM 128
#define NCOL 384

static constexpr float ADJ_SCALE = 4096.0f;
static constexpr float INV_SCALE = 1.0f / 4096.0f;

// ---------------- device scratch (static, no allocations) ----------------
__device__ __half g_hh[NTOT * FDIM];       // h0|h1|h2 fp16
__device__ __half g_wcat[3 * FDIM * NCOL]; // per-j: [128][384] with col block i
__device__ __half g_T[NTOT * NCOL];        // T_j = h_j @ Wcat_j
__device__ __half g_Y[NTOT * NCOL];        // gathered/scattered B operand [k][384]
__device__ float  g_Z[NTOT * NCOL];        // split-K accumulation target
__device__ int    g_inv0[NL0];
__device__ int    g_inv1[NL1];

__device__ __forceinline__ void cp16(const void* dst, const void* src, bool full) {
    unsigned d = (unsigned)__cvta_generic_to_shared(dst);
    int n = full ? 16 : 0;
    asm volatile("cp.async.cg.shared.global [%0], [%1], 16, %2;\n" :: "r"(d), "l"(src), "r"(n));
}

// ---------------- prep kernel ----------------
__global__ void k_prep_h(const float* __restrict__ h0, const float* __restrict__ h1,
                         const float* __restrict__ h2, const float* __restrict__ Ws) {
    int t = blockIdx.x * blockDim.x + threadIdx.x;
    if (t < 448000) {
        int e = t * 4;
        const float* src;
        if (e < 1024000) src = h0 + e;
        else if (e < 1536000) src = h1 + (e - 1024000);
        else src = h2 + (e - 1536000);
        float4 v = *(const float4*)src;
        *(__half2*)(g_hh + e)     = __floats2half2_rn(v.x, v.y);
        *(__half2*)(g_hh + e + 2) = __floats2half2_rn(v.z, v.w);
    }
    if (t < 3 * FDIM * NCOL) {
        int j = t / 49152;
        int rem = t % 49152;
        int k = rem / 384;
        int col = rem % 384;
        int i = col >> 7;
        int c = col & 127;
        g_wcat[t] = __float2half(Ws[(((size_t)(i * 3 + j) * 128) + k) * 128 + c]);
    }
    if (t < (NTOT * NCOL) / 4) {
        ((float4*)g_Z)[t] = make_float4(0.f, 0.f, 0.f, 0.f);
    }
    if (t < NL0) g_inv0[t] = -1;
    if (t < NL1) g_inv1[t] = -1;
}

// Gather T -> Y (one 16B chunk per thread)
__global__ void k_gather_y(const int* __restrict__ idx0, const int* __restrict__ idx1) {
    int tid = blockIdx.x * blockDim.x + threadIdx.x;
    if (tid >= NTOT * 3 * 16) return;
    int seg = tid & 15;
    int rest = tid >> 4;
    int j = rest % 3;
    int rg = rest / 3;
    int i, r;
    if (rg < NL0)            { i = 0; r = rg; }
    else if (rg < NL0 + NL1) { i = 1; r = rg - NL0; }
    else                     { i = 2; r = rg - NL0 - NL1; }
    int s = -1;
    if (i == 0) {
        if (j == 0) s = r;
        else if (j == 1) s = g_inv0[r];
        else { int t0 = g_inv0[r]; s = (t0 >= 0) ? g_inv1[t0] : -1; }
    } else if (i == 1) {
        if (j == 0) s = idx0[r];
        else if (j == 1) s = r;
        else s = g_inv1[r];
    } else {
        if (j == 0) s = idx0[idx1[r]];
        else if (j == 1) s = idx1[r];
        else s = r;
    }
    uint4 v = make_uint4(0u, 0u, 0u, 0u);
    if (s >= 0) {
        int srow = (j == 0 ? 0 : (j == 1 ? NL0 : NL0 + NL1)) + s;
        v = *(const uint4*)(g_T + (size_t)srow * NCOL + i * 128 + seg * 8);
    }
    *(uint4*)(g_Y + (size_t)rg * NCOL + j * 128 + seg * 8) = v;
}

// ---------------- shared GEMM tiling constants ----------------
#define BM 64
#define BK 32
#define APITCH 40   // halves per A fp16 smem row (pad 8)
#define BPITCH 392  // halves per B smem row (pad 8)
#define STG_HALVES (BM * APITCH + BK * BPITCH)  // 15104 (gemm1 stage)
#define SMEM1_BYTES (3 * STG_HALVES * 2)        // 90624

// gemm2 stage: [A32: 64x36 fp32 = 9216][A16: 64x40 half = 5120][B: 32x392 half = 25088]
#define A32PITCH 36
#define STG2_A16_OFF 9216
#define STG2_B_OFF 14336
#define STG2_BYTES 39424
#define NSTG2 4
#define SMEM2_BYTES (NSTG2 * STG2_BYTES)        // 157696

// ---- 256-thread compute: warp tile 32x96 (gemm1, R9-proven) ----
#define COMPUTE_TILE(as, bs)                                                          \
    {                                                                                 \
        uint32_t af[2][2][4];                                                         \
        uint32_t bf[2][6][4];                                                         \
        _Pragma("unroll")                                                             \
        for (int kk = 0; kk < 2; ++kk) {                                              \
            _Pragma("unroll")                                                         \
            for (int mt = 0; mt < 2; ++mt) {                                          \
                __half* p = (as) + (size_t)(wm * 32 + mt * 16 + a_row) * APITCH       \
                            + kk * 16 + a_col8;                                       \
                unsigned sp = (unsigned)__cvta_generic_to_shared(p);                  \
                asm volatile("ldmatrix.sync.aligned.m8n8.x4.shared.b16 "              \
                             "{%0,%1,%2,%3}, [%4];\n"                                 \
                             : "=r"(af[kk][mt][0]), "=r"(af[kk][mt][1]),              \
                               "=r"(af[kk][mt][2]), "=r"(af[kk][mt][3])               \
                             : "r"(sp));                                              \
            }                                                                         \
            _Pragma("unroll")                                                         \
            for (int ntp = 0; ntp < 6; ++ntp) {                                       \
                __half* p = (bs) + (size_t)(kk * 16 + bx4_row) * BPITCH               \
                            + bx4_col + ntp * 16;                                     \
                unsigned sp = (unsigned)__cvta_generic_to_shared(p);                  \
                asm volatile("ldmatrix.sync.aligned.m8n8.x4.trans.shared.b16 "        \
                             "{%0,%1,%2,%3}, [%4];\n"                                 \
                             : "=r"(bf[kk][ntp][0]), "=r"(bf[kk][ntp][1]),            \
                               "=r"(bf[kk][ntp][2]), "=r"(bf[kk][ntp][3])             \
                             : "r"(sp));                                              \
            }                                                                         \
        }                                                                             \
        _Pragma("unroll")                                                             \
        for (int kk = 0; kk < 2; ++kk) {                                              \
            _Pragma("unroll")                                                         \
            for (int ntp = 0; ntp < 6; ++ntp) {                                       \
                _Pragma("unroll")                                                     \
                for (int mt = 0; mt < 2; ++mt) {                                      \
                    asm volatile(                                                     \
                        "mma.sync.aligned.m16n8k16.row.col.f32.f16.f16.f32 "          \
                        "{%0,%1,%2,%3}, {%4,%5,%6,%7}, {%8,%9}, {%0,%1,%2,%3};\n"     \
                        : "+f"(acc[mt][2 * ntp][0]), "+f"(acc[mt][2 * ntp][1]),       \
                          "+f"(acc[mt][2 * ntp][2]), "+f"(acc[mt][2 * ntp][3])        \
                        : "r"(af[kk][mt][0]), "r"(af[kk][mt][1]),                     \
                          "r"(af[kk][mt][2]), "r"(af[kk][mt][3]),                     \
                          "r"(bf[kk][ntp][0]), "r"(bf[kk][ntp][1]));                  \
                    asm volatile(                                                     \
                        "mma.sync.aligned.m16n8k16.row.col.f32.f16.f16.f32 "          \
                        "{%0,%1,%2,%3}, {%4,%5,%6,%7}, {%8,%9}, {%0,%1,%2,%3};\n"     \
                        : "+f"(acc[mt][2 * ntp + 1][0]), "+f"(acc[mt][2 * ntp + 1][1]),\
                          "+f"(acc[mt][2 * ntp + 1][2]), "+f"(acc[mt][2 * ntp + 1][3])\
                        : "r"(af[kk][mt][0]), "r"(af[kk][mt][1]),                     \
                          "r"(af[kk][mt][2]), "r"(af[kk][mt][3]),                     \
                          "r"(bf[kk][ntp][2]), "r"(bf[kk][ntp][3]));                  \
                }                                                                     \
            }                                                                         \
        }                                                                             \
    }

// ---- 512-thread compute: warp tile 32x48 (gemm2) ----
#define COMPUTE_TILE48(as, bs)                                                        \
    {                                                                                 \
        uint32_t af[2][2][4];                                                         \
        uint32_t bf[2][3][4];                                                         \
        _Pragma("unroll")                                                             \
        for (int kk = 0; kk < 2; ++kk) {                                              \
            _Pragma("unroll")                                                         \
            for (int mt = 0; mt < 2; ++mt) {                                          \
                __half* p = (as) + (size_t)(wm * 32 + mt * 16 + a_row) * APITCH       \
                            + kk * 16 + a_col8;                                       \
                unsigned sp = (unsigned)__cvta_generic_to_shared(p);                  \
                asm volatile("ldmatrix.sync.aligned.m8n8.x4.shared.b16 "              \
                             "{%0,%1,%2,%3}, [%4];\n"                                 \
                             : "=r"(af[kk][mt][0]), "=r"(af[kk][mt][1]),              \
                               "=r"(af[kk][mt][2]), "=r"(af[kk][mt][3])               \
                             : "r"(sp));                                              \
            }                                                                         \
            _Pragma("unroll")                                                         \
            for (int ntp = 0; ntp < 3; ++ntp) {                                       \
                __half* p = (bs) + (size_t)(kk * 16 + bx4_row) * BPITCH               \
                            + bx4_col + ntp * 16;                                     \
                unsigned sp = (unsigned)__cvta_generic_to_shared(p);                  \
                asm volatile("ldmatrix.sync.aligned.m8n8.x4.trans.shared.b16 "        \
                             "{%0,%1,%2,%3}, [%4];\n"                                 \
                             : "=r"(bf[kk][ntp][0]), "=r"(bf[kk][ntp][1]),            \
                               "=r"(bf[kk][ntp][2]), "=r"(bf[kk][ntp][3])             \
                             : "r"(sp));                                              \
            }                                                                         \
        }                                                                             \
        _Pragma("unroll")                                                             \
        for (int kk = 0; kk < 2; ++kk) {                                              \
            _Pragma("unroll")                                                         \
            for (int ntp = 0; ntp < 3; ++ntp) {                                       \
                _Pragma("unroll")                                                     \
                for (int mt = 0; mt < 2; ++mt) {                                      \
                    asm volatile(                                                     \
                        "mma.sync.aligned.m16n8k16.row.col.f32.f16.f16.f32 "          \
                        "{%0,%1,%2,%3}, {%4,%5,%6,%7}, {%8,%9}, {%0,%1,%2,%3};\n"     \
                        : "+f"(acc[mt][2 * ntp][0]), "+f"(acc[mt][2 * ntp][1]),       \
                          "+f"(acc[mt][2 * ntp][2]), "+f"(acc[mt][2 * ntp][3])        \
                        : "r"(af[kk][mt][0]), "r"(af[kk][mt][1]),                     \
                          "r"(af[kk][mt][2]), "r"(af[kk][mt][3]),                     \
                          "r"(bf[kk][ntp][0]), "r"(bf[kk][ntp][1]));                  \
                    asm volatile(                                                     \
                        "mma.sync.aligned.m16n8k16.row.col.f32.f16.f16.f32 "          \
                        "{%0,%1,%2,%3}, {%4,%5,%6,%7}, {%8,%9}, {%0,%1,%2,%3};\n"     \
                        : "+f"(acc[mt][2 * ntp + 1][0]), "+f"(acc[mt][2 * ntp + 1][1]),\
                          "+f"(acc[mt][2 * ntp + 1][2]), "+f"(acc[mt][2 * ntp + 1][3])\
                        : "r"(af[kk][mt][0]), "r"(af[kk][mt][1]),                     \
                          "r"(af[kk][mt][2]), "r"(af[kk][mt][3]),                     \
                          "r"(bf[kk][ntp][2]), "r"(bf[kk][ntp][3]));                  \
                }                                                                     \
            }                                                                         \
        }                                                                             \
    }

// ---------------- stage-1 GEMM (R9-proven) + folded scatter_inv ----------------
struct Gemm1Seg { int M, tileStart; long long Aoff, Boff, Coff; };
struct Gemm1Cfg { Gemm1Seg seg[3]; };

__global__ void __launch_bounds__(256, 1) k_gemm1(Gemm1Cfg cfg,
                                                  const int* __restrict__ idx0,
                                                  const int* __restrict__ idx1) {
    extern __shared__ __align__(16) char smem_raw[];
    __half* smem = (__half*)smem_raw;

    int tid = threadIdx.x;
    int bxi = blockIdx.x;

    // folded scatter_inv (prep already set inv=-1; gather runs after this kernel)
    int gtid = bxi * 256 + tid;
    if (gtid < NL1) g_inv0[idx0[gtid]] = gtid;
    if (gtid < NL2) g_inv1[idx1[gtid]] = gtid;

    int s = 0;
    if (bxi >= cfg.seg[1].tileStart) s = 1;
    if (bxi >= cfg.seg[2].tileStart) s = 2;
    Gemm1Seg sg = cfg.seg[s];
    int tile = bxi - sg.tileStart;
    int row0 = tile * BM;
    int M = sg.M, K = 128;
    const __half* A = g_hh + sg.Aoff;
    const __half* B = g_wcat + sg.Boff;

    int lane = tid & 31, wid = tid >> 5;
    int wm = wid >> 2, wn = wid & 3;

    int am = tid >> 2, aseg = tid & 3;
    int br[6], bseg[6];
#pragma unroll
    for (int it = 0; it < 6; ++it) { int c = tid + it * 256; br[it] = c / 48; bseg[it] = c % 48; }

    int KT = K / BK; // 4

    auto load_tile = [&](int kt, int st) {
        __half* as = smem + st * STG_HALVES;
        __half* bs = as + BM * APITCH;
        int k0 = kt * BK;
        {
            int grow = row0 + am;
            bool p = (grow < M);
            const __half* src = p ? (A + (size_t)grow * K + k0 + aseg * 8) : A;
            cp16(as + am * APITCH + aseg * 8, src, p);
        }
#pragma unroll
        for (int it = 0; it < 6; ++it) {
            int kr = k0 + br[it];
            cp16(bs + br[it] * BPITCH + bseg[it] * 8, B + (size_t)kr * NCOL + bseg[it] * 8, true);
        }
    };

    load_tile(0, 0);
    asm volatile("cp.async.commit_group;\n");
    load_tile(1, 1);
    asm volatile("cp.async.commit_group;\n");

    float acc[2][12][4] = {};
    int a_row = lane & 15;
    int a_col8 = 8 * (lane >> 4);
    int grp = lane >> 3;
    int bx4_row = (grp & 1) * 8 + (lane & 7);
    int bx4_col = wn * 96 + (grp >> 1) * 8;

    for (int kt = 0; kt < KT; ++kt) {
        asm volatile("cp.async.wait_group 1;\n");
        __syncthreads();
        int nx = kt + 2;
        if (nx < KT) load_tile(nx, nx % 3);
        asm volatile("cp.async.commit_group;\n");

        __half* as = smem + (kt % 3) * STG_HALVES;
        __half* bs = as + BM * APITCH;
        COMPUTE_TILE(as, bs)
    }

    int g = lane >> 2, tg = lane & 3;
    __half* C = g_T + sg.Coff;
#pragma unroll
    for (int mt = 0; mt < 2; ++mt) {
        int r1 = row0 + wm * 32 + mt * 16 + g;
        int r2 = r1 + 8;
#pragma unroll
        for (int nt = 0; nt < 12; ++nt) {
            int col = wn * 96 + nt * 8 + tg * 2;
            if (r1 < M) *(__half2*)(C + (size_t)r1 * NCOL + col) =
                __floats2half2_rn(acc[mt][nt][0], acc[mt][nt][1]);
            if (r2 < M) *(__half2*)(C + (size_t)r2 * NCOL + col) =
                __floats2half2_rn(acc[mt][nt][2], acc[mt][nt][3]);
        }
    }
}

// ---------------- stage-2 GEMM: 512 threads, split-K, fused A-convert, atomic Z ----------------
// Piece map (grid 408) identical to R12; max 2 contributors per Z element -> deterministic.
__global__ void __launch_bounds__(512, 1) k_gemm2(const float* __restrict__ adj0,
                                                  const float* __restrict__ adj1,
                                                  const float* __restrict__ adj2) {
    extern __shared__ __align__(16) char smem_raw[];

    int tid = threadIdx.x;
    int bxi = blockIdx.x;

    const float* A;
    int M, K, rowBase, row0, kbeg, kend;
    if (bxi < 250) {
        A = adj0; M = NL0; K = NL0; rowBase = 0;
        row0 = (bxi >> 1) * BM;
        kbeg = (bxi & 1) ? 4000 : 0;
        kend = (bxi & 1) ? 8000 : 4000;
    } else if (bxi < 376) {
        int idx = bxi - 250;
        A = adj1; M = NL1; K = NL1; rowBase = NL0;
        row0 = (idx >> 1) * BM;
        kbeg = (idx & 1) ? 2016 : 0;
        kend = (idx & 1) ? 4000 : 2016;
    } else {
        A = adj2; M = NL2; K = NL2; rowBase = NL0 + NL1;
        row0 = (bxi - 376) * BM;
        kbeg = 0; kend = 2000;
    }
    const __half* B = g_Y + (size_t)rowBase * NCOL;

    int lane = tid & 31, wid = tid >> 5;
    int wm = wid >> 3, wn = wid & 7;       // 2m x 8n warp grid, tile 32x48

    int arow = tid >> 3, acg = (tid & 7) * 4;  // A32: one 16B chunk per thread
    int br[3], bseg[3];
#pragma unroll
    for (int it = 0; it < 3; ++it) { int c = tid + it * 512; br[it] = c / 48; bseg[it] = c % 48; }

    int KT = (kend - kbeg + BK - 1) / BK;

    auto A32p = [&](int st) { return (float*)(smem_raw + st * STG2_BYTES); };
    auto A16p = [&](int st) { return (__half*)(smem_raw + st * STG2_BYTES + STG2_A16_OFF); };
    auto Bp   = [&](int st) { return (__half*)(smem_raw + st * STG2_BYTES + STG2_B_OFF); };

    auto load_tile = [&](int kt, int st) {
        int k0 = kbeg + kt * BK;
        {
            int grow = row0 + arow;
            int gc = k0 + acg;
            bool p = (grow < M) && (gc < kend);   // kend % 4 == 0, chunk test exact
            const float* src = p ? (A + (size_t)grow * K + gc) : A;
            cp16(A32p(st) + arow * A32PITCH + acg, src, p);
        }
        __half* bs = Bp(st);
#pragma unroll
        for (int it = 0; it < 3; ++it) {
            int kr = k0 + br[it];
            bool p = (kr < kend);
            const __half* src = p ? (B + (size_t)kr * NCOL + bseg[it] * 8) : B;
            cp16(bs + br[it] * BPITCH + bseg[it] * 8, src, p);
        }
    };

    // smem fp32 -> smem fp16 (x ADJ_SCALE), 4 floats per thread
    auto convert = [&](int st) {
        int row = tid >> 3, c4 = tid & 7;
        const float* src = A32p(st) + row * A32PITCH + c4 * 4;
        float4 v = *(const float4*)src;
        uint2 p;
        *(__half2*)&p.x = __floats2half2_rn(v.x * ADJ_SCALE, v.y * ADJ_SCALE);
        *(__half2*)&p.y = __floats2half2_rn(v.z * ADJ_SCALE, v.w * ADJ_SCALE);
        *(uint2*)(A16p(st) + row * APITCH + c4 * 4) = p;
    };

    // prologue: fill 3 of 4 stages; convert tile 0
    load_tile(0, 0);
    asm volatile("cp.async.commit_group;\n");
    load_tile(1, 1);
    asm volatile("cp.async.commit_group;\n");
    load_tile(2, 2);
    asm volatile("cp.async.commit_group;\n");
    asm volatile("cp.async.wait_group 2;\n");   // tile 0 landed
    __syncthreads();
    convert(0);

    float acc[2][6][4] = {};
    int a_row = lane & 15;
    int a_col8 = 8 * (lane >> 4);
    int grp = lane >> 3;
    int bx4_row = (grp & 1) * 8 + (lane & 7);
    int bx4_col = wn * 48 + (grp >> 1) * 8;

    for (int kt = 0; kt < KT; ++kt) {
        asm volatile("cp.async.wait_group 1;\n");   // tile kt+1 landed
        __syncthreads();                            // convert(kt) visible; stage reuse safe
        if (kt + 1 < KT) convert((kt + 1) & 3);     // convert next tile
        __half* as = A16p(kt & 3);
        __half* bs = Bp(kt & 3);
        COMPUTE_TILE48(as, bs)
        int nx = kt + 3;
        if (nx < KT) load_tile(nx, nx & 3);
        asm volatile("cp.async.commit_group;\n");
    }

    asm volatile("cp.async.wait_group 0;\n");
    __syncthreads();

    // partial accumulation into g_Z (raw scaled values)
    float* Zb = g_Z + (size_t)(rowBase + row0) * NCOL;
    int g = lane >> 2, tg = lane & 3;
#pragma unroll
    for (int mt = 0; mt < 2; ++mt) {
        int r1 = wm * 32 + mt * 16 + g;
        int r2 = r1 + 8;
        bool p1 = (row0 + r1) < M;
        bool p2 = (row0 + r2) < M;
#pragma unroll
        for (int nt = 0; nt < 6; ++nt) {
            int col = wn * 48 + nt * 8 + tg * 2;
            if (p1) {
                atomicAdd(Zb + (size_t)r1 * NCOL + col,     acc[mt][nt][0]);
                atomicAdd(Zb + (size_t)r1 * NCOL + col + 1, acc[mt][nt][1]);
            }
            if (p2) {
                atomicAdd(Zb + (size_t)r2 * NCOL + col,     acc[mt][nt][2]);
                atomicAdd(Zb + (size_t)r2 * NCOL + col + 1, acc[mt][nt][3]);
            }
        }
    }
}

// ---------------- final epilogue: out = sum_j relu(Z_block_j * inv_scale + b) ----------------
__global__ void k_final(const float* __restrict__ bs, float* __restrict__ out) {
    int tid = blockIdx.x * blockDim.x + threadIdx.x;
    if (tid >= NTOT * FDIM) return;
    int r = tid >> 7;
    int c = tid & 127;
    int i = (r < NL0) ? 0 : ((r < NL0 + NL1) ? 1 : 2);
    float acc = 0.0f;
#pragma unroll
    for (int j = 0; j < 3; ++j) {
        float z = g_Z[(size_t)r * NCOL + j * 128 + c] * INV_SCALE + bs[(i * 3 + j) * 128 + c];
        acc += fmaxf(z, 0.0f);
    }
    out[tid] = acc;
}

// ---------------- host launch ----------------
extern "C" void kernel_launch(void* const* d_in, const int* in_sizes, int n_in,
                              void* d_out, int out_size) {
    const float* adj0 = (const float*)d_in[0];
    const float* adj1 = (const float*)d_in[1];
    const float* adj2 = (const float*)d_in[2];
    const float* h0   = (const float*)d_in[3];
    const float* h1   = (const float*)d_in[4];
    const float* h2   = (const float*)d_in[5];
    const int*   idx0 = (const int*)d_in[6];
    const int*   idx1 = (const int*)d_in[7];
    const float* Ws   = (const float*)d_in[8];
    const float* bsp  = (const float*)d_in[9];
    float* out = (float*)d_out;

    cudaFuncSetAttribute(k_gemm1, cudaFuncAttributeMaxDynamicSharedMemorySize, SMEM1_BYTES);
    cudaFuncSetAttribute(k_gemm2, cudaFuncAttributeMaxDynamicSharedMemorySize, SMEM2_BYTES);

    k_prep_h<<<5250, 256>>>(h0, h1, h2, Ws);       // #0 (zeroes g_Z, inits inv)

    Gemm1Cfg c1;
    c1.seg[0] = { NL0, 0,   0,       0,     0 };
    c1.seg[1] = { NL1, 125, 1024000, 49152, 3072000 };
    c1.seg[2] = { NL2, 188, 1536000, 98304, 4608000 };
    k_gemm1<<<220, 256, SMEM1_BYTES>>>(c1, idx0, idx1);  // #1 (incl. scatter_inv)

    k_gather_y<<<2625, 256>>>(idx0, idx1);         // #2

    k_gemm2<<<408, 512, SMEM2_BYTES>>>(adj0, adj1, adj2);  // #3 (ncu target)

    k_final<<<7000, 256>>>(bsp, out);              // #4
}